// round 6
// baseline (speedup 1.0000x reference)
#include <cuda_runtime.h>
#include <cstdint>
#include <math.h>

#define NE 32
#define TOPK 8
#define HD 2048
#define ID 1024
#define NT 4096
#define TE (NT*TOPK)
#define MAXT 288

__device__ int g_cnt[NE], g_off[NE];
__device__ int g_tok[TE], g_adp[TE], g_pos[TE];
__device__ int g_te[MAXT], g_tm[MAXT];
__device__ int g_nt;
__device__ float g_Zgu[(size_t)TE*64];
__device__ float g_Zd[(size_t)TE*32];
__device__ float g_G[(size_t)TE*ID];   // gate, then h = silu(g)*u
__device__ float g_O[(size_t)TE*HD];

__device__ __forceinline__ uint32_t smem_u32(const void* p) {
    uint32_t a;
    asm("{ .reg .u64 t; cvta.to.shared.u64 t, %1; cvt.u32.u64 %0, t; }" : "=r"(a) : "l"(p));
    return a;
}
__device__ __forceinline__ uint32_t tf32u(float x) {
    uint32_t u;
    asm("cvt.rna.tf32.f32 %0, %1;" : "=r"(u) : "f"(x));
    return u;
}
__device__ __forceinline__ float tf32f(float x) { return __uint_as_float(tf32u(x)); }
__device__ __forceinline__ void cpa16(uint32_t dst, const float* src) {
    asm volatile("cp.async.cg.shared.global [%0], [%1], 16;" :: "r"(dst), "l"(src) : "memory");
}
__device__ __forceinline__ void cpa_commit() {
    asm volatile("cp.async.commit_group;" ::: "memory");
}
__device__ __forceinline__ void cpa_wait1() {
    asm volatile("cp.async.wait_group 1;" ::: "memory");
}
__device__ __forceinline__ void mma8(float* c, const uint32_t* a, const uint32_t* b) {
    asm volatile(
        "mma.sync.aligned.m16n8k8.row.col.f32.tf32.tf32.f32 "
        "{%0,%1,%2,%3}, {%4,%5,%6,%7}, {%8,%9}, {%0,%1,%2,%3};\n"
        : "+f"(c[0]), "+f"(c[1]), "+f"(c[2]), "+f"(c[3])
        : "r"(a[0]), "r"(a[1]), "r"(a[2]), "r"(a[3]), "r"(b[0]), "r"(b[1]));
}

__global__ void routing_kernel(const int* __restrict__ sel, const int* __restrict__ adp) {
    __shared__ int s_cnt[NE], s_cur[NE];
    int tid = threadIdx.x;
    if (tid < NE) s_cnt[tid] = 0;
    __syncthreads();
    for (int i = tid; i < TE; i += blockDim.x) atomicAdd(&s_cnt[sel[i]], 1);
    __syncthreads();
    if (tid == 0) {
        int acc = 0, idx = 0;
        for (int e = 0; e < NE; e++) {
            int c = s_cnt[e];
            g_cnt[e] = c; g_off[e] = acc; s_cur[e] = acc; acc += c;
            for (int i = 0; i < (c + 127) >> 7; i++) { g_te[idx] = e; g_tm[idx] = i; idx++; }
        }
        g_nt = idx;
    }
    __syncthreads();
    for (int i = tid; i < TE; i += blockDim.x) {
        int e = sel[i];
        int pos = atomicAdd(&s_cur[e], 1);
        int t = i >> 3;
        g_tok[pos] = t; g_adp[pos] = adp[t]; g_pos[i] = pos;
    }
}

// ---- main grouped GEMM: M-tile 128, N-tile 128, 256 threads, 2 CTAs/SM ----
// Out = X @ W[e] + Zmasked @ [B_a0;B_a1]   (LoRA as one extra K-chunk)
// FUSE=1: Out[i] = acc * silu(Out[i])      (up-projection, Out holds gate)
#define XSTG 5120     // 128 rows * 40 floats (tf32, k-interleaved)
#define WSTG 4352     // 32 k * 136 floats (raw fp32)
#define SMM  (512 + 2*XSTG*4 + 2*WSTG*4)

template<int FUSE>
__global__ __launch_bounds__(256, 2)
void mm_main(const float* __restrict__ X, const float* __restrict__ W,
             const float* __restrict__ LB, const float* __restrict__ ZB,
             float* __restrict__ Out, int K, int NW, int ldx, int gather,
             int zld, int zoff)
{
    if ((int)blockIdx.y >= g_nt) return;
    const int e   = g_te[blockIdx.y];
    const int m0  = g_tm[blockIdx.y] << 7;
    const int cnt = g_cnt[e], off = g_off[e];
    const int n0  = blockIdx.x << 7;
    const int tid = threadIdx.x, lane = tid & 31, wid = tid >> 5;
    const int row_base = (wid & 1) << 6;
    const int col_base = (wid >> 1) << 5;

    extern __shared__ char smem[];
    int*   s_src = (int*)smem;
    float* xb = (float*)(smem + 512);
    float* wb = (float*)(smem + 512 + 2 * XSTG * 4);

    if (tid < 128) {
        int p = off + min(m0 + tid, cnt - 1);
        s_src[tid] = gather ? g_tok[p] : p;
    }
    __syncthreads();

    const int KC = K >> 5;
    const int KT = KC + 1;
    const float* Wexp = W + (size_t)e * K * NW;
    const int g8 = (tid & 3) << 3;

    auto ldX = [&](int kc, int grp, float4& t0, float4& t1) {
        int r = (tid >> 2) + (grp << 6);
        const float* src;
        if (kc < KC) {
            src = X + (size_t)s_src[r] * ldx + (kc << 5) + g8;
        } else {
            int p = off + min(m0 + r, cnt - 1);
            src = ZB + (size_t)p * zld + zoff + g8;
        }
        t0 = *(const float4*)src;
        t1 = *(const float4*)(src + 4);
    };
    auto stX = [&](int buf, int grp, const float4& t0, const float4& t1) {
        int r = (tid >> 2) + (grp << 6);
        float* d = xb + buf * XSTG + r * 40 + g8;
        float4 a, b;
        a.x = tf32f(t0.x); a.y = tf32f(t1.x); a.z = tf32f(t0.y); a.w = tf32f(t1.y);
        b.x = tf32f(t0.z); b.y = tf32f(t1.z); b.z = tf32f(t0.w); b.w = tf32f(t1.w);
        *(float4*)d = a; *(float4*)(d + 4) = b;
    };
    const uint32_t wba = smem_u32(wb);
    auto ldW = [&](int kc, int buf) {
        #pragma unroll
        for (int i = 0; i < 4; i++) {
            int u = tid + (i << 8);
            int k = u >> 5, n4 = (u & 31) << 2;
            const float* src;
            if (kc < KC)
                src = Wexp + (size_t)((kc << 5) + k) * NW + n0 + n4;
            else
                src = LB + (((size_t)(k >> 4) * NE + e) * 16 + (k & 15)) * NW + n0 + n4;
            cpa16(wba + (buf * WSTG + k * 136 + n4) * 4, src);
        }
    };

    float acc[4][4][4];
    #pragma unroll
    for (int i = 0; i < 4; i++)
        #pragma unroll
        for (int j = 0; j < 4; j++) { acc[i][j][0]=0.f; acc[i][j][1]=0.f; acc[i][j][2]=0.f; acc[i][j][3]=0.f; }

    float4 x0a, x0b, x1a, x1b;
    // prologue
    ldW(0, 0); cpa_commit();
    ldX(0, 0, x0a, x0b); ldX(0, 1, x1a, x1b);
    stX(0, 0, x0a, x0b); stX(0, 1, x1a, x1b);
    ldW(1, 1); cpa_commit();
    ldX(1, 0, x0a, x0b); ldX(1, 1, x1a, x1b);   // chunk 1 held in regs
    cpa_wait1();
    __syncthreads();

    for (int kc = 0; kc < KT; kc++) {
        const int buf = kc & 1;
        if (kc + 1 < KT) {
            stX(buf ^ 1, 0, x0a, x0b); stX(buf ^ 1, 1, x1a, x1b);
            if (kc + 2 < KT) { ldX(kc + 2, 0, x0a, x0b); ldX(kc + 2, 1, x1a, x1b); }
        }
        const float* xs = xb + buf * XSTG;
        const float* ws = wb + buf * WSTG;
        #pragma unroll
        for (int ks = 0; ks < 4; ks++) {
            const int kk = ks << 3;
            uint32_t A[4][4];
            #pragma unroll
            for (int mf = 0; mf < 4; mf++) {
                int r0 = row_base + (mf << 4) + (lane >> 2);
                float2 lo = *(const float2*)&xs[r0 * 40 + kk + ((lane & 3) << 1)];
                float2 hi = *(const float2*)&xs[(r0 + 8) * 40 + kk + ((lane & 3) << 1)];
                A[mf][0] = __float_as_uint(lo.x);
                A[mf][1] = __float_as_uint(hi.x);
                A[mf][2] = __float_as_uint(lo.y);
                A[mf][3] = __float_as_uint(hi.y);
            }
            uint32_t B[4][2];
            #pragma unroll
            for (int nf = 0; nf < 4; nf++) {
                int cb = col_base + (nf << 3) + (lane >> 2);
                B[nf][0] = tf32u(ws[(kk + (lane & 3)) * 136 + cb]);
                B[nf][1] = tf32u(ws[(kk + (lane & 3) + 4) * 136 + cb]);
            }
            #pragma unroll
            for (int mf = 0; mf < 4; mf++)
                #pragma unroll
                for (int nf = 0; nf < 4; nf++)
                    mma8(acc[mf][nf], A[mf], B[nf]);
        }
        __syncthreads();
        if (kc + 2 < KT) ldW(kc + 2, buf);
        cpa_commit();
        cpa_wait1();
        __syncthreads();
    }

    // epilogue
    #pragma unroll
    for (int mf = 0; mf < 4; mf++) {
        int rl0 = row_base + (mf << 4) + (lane >> 2);
        int rl1 = rl0 + 8;
        bool v0 = (m0 + rl0) < cnt, v1 = (m0 + rl1) < cnt;
        int p0 = off + min(m0 + rl0, cnt - 1);
        int p1 = off + min(m0 + rl1, cnt - 1);
        #pragma unroll
        for (int nf = 0; nf < 4; nf++) {
            int cl = col_base + (nf << 3) + ((lane & 3) << 1);
            if (FUSE) {
                #pragma unroll
                for (int q = 0; q < 2; q++) {
                    if (v0) {
                        size_t i = (size_t)p0 * NW + n0 + cl + q;
                        float g = Out[i];
                        Out[i] = acc[mf][nf][q] * g / (1.f + expf(-g));
                    }
                    if (v1) {
                        size_t i = (size_t)p1 * NW + n0 + cl + q;
                        float g = Out[i];
                        Out[i] = acc[mf][nf][2 + q] * g / (1.f + expf(-g));
                    }
                }
            } else {
                if (v0) *(float2*)(Out + (size_t)p0 * NW + n0 + cl) =
                            make_float2(acc[mf][nf][0], acc[mf][nf][1]);
                if (v1) *(float2*)(Out + (size_t)p1 * NW + n0 + cl) =
                            make_float2(acc[mf][nf][2], acc[mf][nf][3]);
            }
        }
    }
}

// ---- Z kernel: Out[p, n] = adapter-masked (x_p @ A) ----
// N_=64: n<32 from A0 (gate), n>=32 from A1 (up); within 32: n>>4 = adapter.
// N_=32: all from A0 (down), n>>4 = adapter.
template<int N_>
__global__ __launch_bounds__(256)
void mm_z(const float* __restrict__ X, const float* __restrict__ A0,
          const float* __restrict__ A1, float* __restrict__ Out,
          int K, int ldx, int gather)
{
    if ((int)blockIdx.y >= g_nt) return;
    const int e   = g_te[blockIdx.y];
    const int m0  = g_tm[blockIdx.y] << 7;
    const int cnt = g_cnt[e], off = g_off[e];
    const int tid = threadIdx.x, lane = tid & 31, wid = tid >> 5;
    constexpr int MW = (N_ == 64) ? 4 : 8;
    constexpr int MF = 8 / MW;   // 2 or 1
    const int row_base = (wid % MW) * (128 / MW);
    const int col_base = (wid / MW) * 32;
    constexpr int WLD = N_ + 8;

    extern __shared__ char smem[];
    int*   s_src = (int*)smem;
    float* xs = (float*)(smem + 512);
    float* ws = (float*)(smem + 512 + XSTG * 4);

    if (tid < 128) {
        int p = off + min(m0 + tid, cnt - 1);
        s_src[tid] = gather ? g_tok[p] : p;
    }
    __syncthreads();

    const int g8 = (tid & 3) << 3;
    float acc[MF][4][4];
    #pragma unroll
    for (int i = 0; i < MF; i++)
        #pragma unroll
        for (int j = 0; j < 4; j++) { acc[i][j][0]=0.f; acc[i][j][1]=0.f; acc[i][j][2]=0.f; acc[i][j][3]=0.f; }

    const int KC = K >> 5;
    for (int kc = 0; kc < KC; kc++) {
        __syncthreads();
        // X fill
        #pragma unroll
        for (int grp = 0; grp < 2; grp++) {
            int r = (tid >> 2) + (grp << 6);
            const float* src = X + (size_t)s_src[r] * ldx + (kc << 5) + g8;
            float4 t0 = *(const float4*)src;
            float4 t1 = *(const float4*)(src + 4);
            float* d = xs + r * 40 + g8;
            float4 a, b;
            a.x = tf32f(t0.x); a.y = tf32f(t1.x); a.z = tf32f(t0.y); a.w = tf32f(t1.y);
            b.x = tf32f(t0.z); b.y = tf32f(t1.z); b.z = tf32f(t0.w); b.w = tf32f(t1.w);
            *(float4*)d = a; *(float4*)(d + 4) = b;
        }
        // W fill: lora-A gather, raw
        for (int u = tid; u < 32 * N_; u += 256) {
            int n = u & (N_ - 1), k = u >> ((N_ == 64) ? 6 : 5);
            const float* mat = (n < 32) ? A0 : A1;
            int a = (n >> 4) & 1;
            ws[k * WLD + n] = __ldg(mat + (((size_t)a * NE + e) * K + (kc << 5) + k) * 16 + (n & 15));
        }
        __syncthreads();
        #pragma unroll
        for (int ks = 0; ks < 4; ks++) {
            const int kk = ks << 3;
            uint32_t A[MF][4];
            #pragma unroll
            for (int mf = 0; mf < MF; mf++) {
                int r0 = row_base + (mf << 4) + (lane >> 2);
                float2 lo = *(const float2*)&xs[r0 * 40 + kk + ((lane & 3) << 1)];
                float2 hi = *(const float2*)&xs[(r0 + 8) * 40 + kk + ((lane & 3) << 1)];
                A[mf][0] = __float_as_uint(lo.x);
                A[mf][1] = __float_as_uint(hi.x);
                A[mf][2] = __float_as_uint(lo.y);
                A[mf][3] = __float_as_uint(hi.y);
            }
            uint32_t B[4][2];
            #pragma unroll
            for (int nf = 0; nf < 4; nf++) {
                int cb = col_base + (nf << 3) + (lane >> 2);
                B[nf][0] = tf32u(ws[(kk + (lane & 3)) * WLD + cb]);
                B[nf][1] = tf32u(ws[(kk + (lane & 3) + 4) * WLD + cb]);
            }
            #pragma unroll
            for (int mf = 0; mf < MF; mf++)
                #pragma unroll
                for (int nf = 0; nf < 4; nf++)
                    mma8(acc[mf][nf], A[mf], B[nf]);
        }
    }

    #pragma unroll
    for (int mf = 0; mf < MF; mf++) {
        int rl0 = row_base + (mf << 4) + (lane >> 2);
        int rl1 = rl0 + 8;
        int p0 = off + min(m0 + rl0, cnt - 1);
        int p1 = off + min(m0 + rl1, cnt - 1);
        int a0 = g_adp[p0], a1 = g_adp[p1];
        #pragma unroll
        for (int nf = 0; nf < 4; nf++) {
            int cl = col_base + (nf << 3) + ((lane & 3) << 1);
            #pragma unroll
            for (int q = 0; q < 2; q++) {
                int col = cl + q;
                int sla = (col >> 4) & 1;
                Out[(size_t)p0 * N_ + col] = (sla == a0) ? acc[mf][nf][q]     : 0.f;
                Out[(size_t)p1 * N_ + col] = (sla == a1) ? acc[mf][nf][2 + q] : 0.f;
            }
        }
    }
}

__global__ void combine_kernel(const float* __restrict__ rw, float* __restrict__ out) {
    int t = blockIdx.x;
    __shared__ int s_pos[TOPK];
    __shared__ float s_w[TOPK];
    if (threadIdx.x < TOPK) {
        s_pos[threadIdx.x] = g_pos[t*TOPK + threadIdx.x];
        s_w[threadIdx.x]   = rw[t*TOPK + threadIdx.x];
    }
    __syncthreads();
    for (int h = threadIdx.x * 4; h < HD; h += blockDim.x * 4) {
        float4 acc = make_float4(0.f, 0.f, 0.f, 0.f);
        #pragma unroll
        for (int k = 0; k < TOPK; k++) {
            const float4 v = *(const float4*)(g_O + (size_t)s_pos[k]*HD + h);
            float w = s_w[k];
            acc.x += w*v.x; acc.y += w*v.y; acc.z += w*v.z; acc.w += w*v.w;
        }
        *(float4*)(out + (size_t)t*HD + h) = acc;
    }
}

extern "C" void kernel_launch(void* const* d_in, const int* in_sizes, int n_in,
                              void* d_out, int out_size) {
    const float* hidden = (const float*)d_in[0];
    const int*   sel    = (const int*)  d_in[1];
    const float* rw     = (const float*)d_in[2];
    const int*   adp    = (const int*)  d_in[3];
    const float* Wg     = (const float*)d_in[4];
    const float* Ag     = (const float*)d_in[5];
    const float* Bg     = (const float*)d_in[6];
    const float* Wu     = (const float*)d_in[7];
    const float* Au     = (const float*)d_in[8];
    const float* Bu     = (const float*)d_in[9];
    const float* Wd     = (const float*)d_in[10];
    const float* Ad     = (const float*)d_in[11];
    const float* Bd     = (const float*)d_in[12];
    float* out = (float*)d_out;

    static bool init = false;
    if (!init) {
        cudaFuncSetAttribute(mm_main<0>, cudaFuncAttributeMaxDynamicSharedMemorySize, SMM);
        cudaFuncSetAttribute(mm_main<1>, cudaFuncAttributeMaxDynamicSharedMemorySize, SMM);
        init = true;
    }

    float *zgu, *zd, *G, *O;
    cudaGetSymbolAddress((void**)&zgu, g_Zgu);
    cudaGetSymbolAddress((void**)&zd,  g_Zd);
    cudaGetSymbolAddress((void**)&G,   g_G);
    cudaGetSymbolAddress((void**)&O,   g_O);

    const int SMZ64 = 512 + XSTG*4 + 32*72*4;
    const int SMZ32 = 512 + XSTG*4 + 32*40*4;

    routing_kernel<<<1, 1024>>>(sel, adp);

    // Z(gate|up, both adapters), adapter-masked: [TE][64]
    mm_z<64><<<dim3(1, MAXT), 256, SMZ64>>>(hidden, Ag, Au, zgu, HD, HD, 1);
    // gate -> G
    mm_main<0><<<dim3(ID/128, MAXT), 256, SMM>>>(hidden, Wg, Bg, zgu, G, HD, ID, HD, 1, 64, 0);
    // up fused: G = silu(G) * up
    mm_main<1><<<dim3(ID/128, MAXT), 256, SMM>>>(hidden, Wu, Bu, zgu, G, HD, ID, HD, 1, 64, 32);
    // Z(down): [TE][32]
    mm_z<32><<<dim3(1, MAXT), 256, SMZ32>>>(G, Ad, Ad, zd, ID, ID, 0);
    // down -> O
    mm_main<0><<<dim3(HD/128, MAXT), 256, SMM>>>(G, Wd, Bd, zd, O, ID, HD, ID, 0, 32, 0);

    combine_kernel<<<NT, 256>>>(rw, out);
}

// round 8
// speedup vs baseline: 1.2777x; 1.2777x over previous
#include <cuda_runtime.h>
#include <cstdint>
#include <math.h>

#define NE 32
#define TOPK 8
#define HD 2048
#define ID 1024
#define NT 4096
#define TE (NT*TOPK)
#define MAXT 288

#define LDXG 2112     // Xg row: 2048 X | 32 Zg | 32 Zu   (tf32, interleaved)
#define LDGH 1056     // G  row: 1024 h | 32 Zd           (tf32, interleaved)
#define KRGU 2080     // Wt gate/up row: 2048 W + 32 loraB
#define KRD  1056     // Wt down row:    1024 W + 32 loraB

__device__ int g_cnt[NE], g_off[NE];
__device__ int g_tok[TE], g_adp[TE], g_pos[TE];
__device__ int g_te[MAXT], g_tm[MAXT], g_nt;
__device__ float g_Xg[(size_t)TE*LDXG];
__device__ float g_Gh[(size_t)TE*LDGH];
__device__ float g_O [(size_t)TE*HD];
__device__ float g_Wtg[(size_t)NE*ID*KRGU];
__device__ float g_Wtu[(size_t)NE*ID*KRGU];
__device__ float g_Wtd[(size_t)NE*HD*KRD];
__device__ float g_Azt[(size_t)NE*64*HD];
__device__ float g_Adt[(size_t)NE*32*ID];

__device__ __forceinline__ uint32_t smem_u32(const void* p) {
    uint32_t a;
    asm("{ .reg .u64 t; cvta.to.shared.u64 t, %1; cvt.u32.u64 %0, t; }" : "=r"(a) : "l"(p));
    return a;
}
__device__ __forceinline__ float tf32f(float x) {
    uint32_t u;
    asm("cvt.rna.tf32.f32 %0, %1;" : "=r"(u) : "f"(x));
    return __uint_as_float(u);
}
__device__ __forceinline__ void cpa16(uint32_t dst, const float* src) {
    asm volatile("cp.async.cg.shared.global [%0], [%1], 16;" :: "r"(dst), "l"(src) : "memory");
}
__device__ __forceinline__ void cpa_commit() { asm volatile("cp.async.commit_group;" ::: "memory"); }
__device__ __forceinline__ void cpa_wait1()  { asm volatile("cp.async.wait_group 1;" ::: "memory"); }
__device__ __forceinline__ void mma8(float* c, const uint32_t* a, const uint32_t* b) {
    asm volatile(
        "mma.sync.aligned.m16n8k8.row.col.f32.tf32.tf32.f32 "
        "{%0,%1,%2,%3}, {%4,%5,%6,%7}, {%8,%9}, {%0,%1,%2,%3};\n"
        : "+f"(c[0]), "+f"(c[1]), "+f"(c[2]), "+f"(c[3])
        : "r"(a[0]), "r"(a[1]), "r"(a[2]), "r"(a[3]), "r"(b[0]), "r"(b[1]));
}
// stored position of original k=j within each 8-group (k-pair interleave)
__device__ __forceinline__ int pkf(int j) {
    return (j & ~7) | (((j & 3) << 1) | ((j >> 2) & 1));
}

// ---------------- routing ----------------
__global__ void routing_kernel(const int* __restrict__ sel, const int* __restrict__ adp) {
    __shared__ int s_cnt[NE], s_cur[NE];
    int tid = threadIdx.x;
    if (tid < NE) s_cnt[tid] = 0;
    __syncthreads();
    for (int i = tid; i < TE; i += blockDim.x) atomicAdd(&s_cnt[sel[i]], 1);
    __syncthreads();
    if (tid == 0) {
        int acc = 0, idx = 0;
        for (int e = 0; e < NE; e++) {
            int c = s_cnt[e];
            g_cnt[e] = c; g_off[e] = acc; s_cur[e] = acc; acc += c;
            for (int i = 0; i < (c + 127) >> 7; i++) { g_te[idx] = e; g_tm[idx] = i; idx++; }
        }
        g_nt = idx;
    }
    __syncthreads();
    for (int i = tid; i < TE; i += blockDim.x) {
        int e = sel[i];
        int pos = atomicAdd(&s_cur[e], 1);
        int t = i >> 3;
        g_tok[pos] = t; g_adp[pos] = adp[t]; g_pos[i] = pos;
    }
}

// ---------------- X pre-pass: gather + tf32 + interleave ----------------
__global__ void xconv(const float* __restrict__ hidden) {
    int p = blockIdx.x, t = threadIdx.x;
    const float* src = hidden + (size_t)g_tok[p] * HD + (t << 3);
    float4 a = *(const float4*)src, b = *(const float4*)(src + 4);
    float* d = g_Xg + (size_t)p * LDXG + (t << 3);
    *(float4*)d       = make_float4(tf32f(a.x), tf32f(b.x), tf32f(a.y), tf32f(b.y));
    *(float4*)(d + 4) = make_float4(tf32f(a.z), tf32f(b.z), tf32f(a.w), tf32f(b.w));
}

// ---------------- W pre-pass: transpose + tf32 + interleave + append loraB rows ----------------
__global__ void wconv(const float* __restrict__ W, const float* __restrict__ B,
                      float* __restrict__ Wt, int K, int N, int KR)
{
    __shared__ float s[32][132];
    int e = blockIdx.z, ky = blockIdx.y, n0 = blockIdx.x << 7;
    int tid = threadIdx.x;
    int KCn = K >> 5;
    #pragma unroll
    for (int i = 0; i < 4; i++) {
        int u = tid + (i << 8);
        int kk = u >> 5, c = (u & 31) << 2;
        const float* src;
        if (ky < KCn) src = W + ((size_t)e * K + (ky << 5) + kk) * N + n0 + c;
        else          src = B + (((size_t)(kk >> 4) * NE + e) * 16 + (kk & 15)) * N + n0 + c;
        float4 v = *(const float4*)src;
        s[kk][c] = v.x; s[kk][c+1] = v.y; s[kk][c+2] = v.z; s[kk][c+3] = v.w;
    }
    __syncthreads();
    const int ipk[8] = {0, 4, 1, 5, 2, 6, 3, 7};
    #pragma unroll
    for (int i = 0; i < 4; i++) {
        int u = tid + (i << 8);
        int n = u >> 3, c4 = u & 7;
        float4 v;
        float* pv = &v.x;
        #pragma unroll
        for (int q = 0; q < 4; q++) {
            int j = (c4 << 2) + q;
            int k = (j & ~7) + ipk[j & 7];
            pv[q] = tf32f(s[k][n]);
        }
        *(float4*)(Wt + ((size_t)e * N + n0 + n) * KR + (ky << 5) + (c4 << 2)) = v;
    }
}

// ---------------- loraA pre-pass ----------------
__global__ void aconv(const float* __restrict__ Ag, const float* __restrict__ Au,
                      const float* __restrict__ Ad)
{
    int e = blockIdx.x, which = blockIdx.y, tid = threadIdx.x;
    int K = (which == 2) ? ID : HD;
    const float* A = (which == 0) ? Ag : (which == 1) ? Au : Ad;
    for (int u = tid; u < (K << 5); u += 256) {
        int n = u >> ((which == 2) ? 10 : 11);
        int k = u & (K - 1);
        int a = n >> 4, r = n & 15;
        float v = tf32f(__ldg(A + (((size_t)a * NE + e) * K + k) * 16 + r));
        int pk = pkf(k);
        if (which == 2) g_Adt[((size_t)e * 32 + n) * ID + pk] = v;
        else            g_Azt[((size_t)e * 64 + (which << 5) + n) * HD + pk] = v;
    }
}

// ---------------- unified tensor-core grouped GEMM ----------------
// EPI 0: plain store; 1: h=silu(prev)*acc (tf32); 2: masked Zgu->Xg; 3: masked Zd->Gh
// ILV 1: output columns stored k-pair-interleaved (for buffers later consumed as GEMM X input)
template<int N_, int EPI, int ILV>
__global__ __launch_bounds__(256, 2)
void mm(const float* __restrict__ X, int ldx,
        const float* __restrict__ Wt, int KR, int NWT,
        int KC, int KT, int zbase,
        float* __restrict__ Out, int ldo)
{
    if ((int)blockIdx.y >= g_nt) return;
    const int e   = g_te[blockIdx.y];
    const int m0  = g_tm[blockIdx.y] << 7;
    const int cnt = g_cnt[e], off = g_off[e];
    const int n0  = blockIdx.x * N_;
    const int tid = threadIdx.x, lane = tid & 31, wid = tid >> 5;
    constexpr int MW = 256 / N_;
    constexpr int MF = N_ / 32;
    constexpr int XS = 128 * 40;
    constexpr int WS = N_ * 40;
    constexpr int STG = XS + WS;
    const int row_base = (wid % MW) * (128 / MW);
    const int col_base = (wid / MW) * 32;

    extern __shared__ float sm[];
    const uint32_t smb = smem_u32(sm);
    const float* Wte = Wt + ((size_t)e * NWT + n0) * KR;

    auto issue = [&](int kc, int buf) {
        const int xoff = (kc < KC) ? (kc << 5) : zbase;
        #pragma unroll
        for (int i = 0; i < 4; i++) {
            int u = tid + (i << 8);
            int r = u >> 3, c4 = u & 7;
            int p = off + min(m0 + r, cnt - 1);
            cpa16(smb + ((buf * STG + r * 40 + (c4 << 2)) << 2),
                  X + (size_t)p * ldx + xoff + (c4 << 2));
        }
        const int kr = kc << 5;
        #pragma unroll
        for (int i = 0; i < N_ / 32; i++) {
            int u = tid + (i << 8);
            int n = u >> 3, c4 = u & 7;
            cpa16(smb + ((buf * STG + XS + n * 40 + (c4 << 2)) << 2),
                  Wte + (size_t)n * KR + kr + (c4 << 2));
        }
    };

    float acc[MF][4][4];
    #pragma unroll
    for (int i = 0; i < MF; i++)
        #pragma unroll
        for (int j = 0; j < 4; j++) { acc[i][j][0]=0.f; acc[i][j][1]=0.f; acc[i][j][2]=0.f; acc[i][j][3]=0.f; }

    issue(0, 0); cpa_commit();
    if (KT > 1) issue(1, 1);
    cpa_commit();

    for (int kc = 0; kc < KT; kc++) {
        cpa_wait1();
        __syncthreads();
        const int buf = kc & 1;
        const float* xs = sm + buf * STG;
        const float* ws = sm + buf * STG + XS;
        #pragma unroll
        for (int ks = 0; ks < 4; ks++) {
            const int kk = ks << 3;
            const int ko = kk + ((lane & 3) << 1);
            uint32_t A[MF][4];
            #pragma unroll
            for (int mf = 0; mf < MF; mf++) {
                int r0 = row_base + (mf << 4) + (lane >> 2);
                float2 lo = *(const float2*)&xs[r0 * 40 + ko];
                float2 hi = *(const float2*)&xs[(r0 + 8) * 40 + ko];
                A[mf][0] = __float_as_uint(lo.x);
                A[mf][1] = __float_as_uint(hi.x);
                A[mf][2] = __float_as_uint(lo.y);
                A[mf][3] = __float_as_uint(hi.y);
            }
            uint32_t B[4][2];
            #pragma unroll
            for (int nf = 0; nf < 4; nf++) {
                int cb = col_base + (nf << 3) + (lane >> 2);
                float2 bb = *(const float2*)&ws[cb * 40 + ko];
                B[nf][0] = __float_as_uint(bb.x);
                B[nf][1] = __float_as_uint(bb.y);
            }
            #pragma unroll
            for (int mf = 0; mf < MF; mf++)
                #pragma unroll
                for (int nf = 0; nf < 4; nf++)
                    mma8(acc[mf][nf], A[mf], B[nf]);
        }
        __syncthreads();
        if (kc + 2 < KT) issue(kc + 2, buf);
        cpa_commit();
    }

    // ---------------- epilogue ----------------
    #pragma unroll
    for (int mf = 0; mf < MF; mf++) {
        int rl0 = row_base + (mf << 4) + (lane >> 2);
        int rl1 = rl0 + 8;
        bool v0 = (m0 + rl0) < cnt, v1 = (m0 + rl1) < cnt;
        int p0 = off + min(m0 + rl0, cnt - 1);
        int p1 = off + min(m0 + rl1, cnt - 1);
        int a0 = 0, a1 = 0;
        if (EPI >= 2) { a0 = g_adp[p0]; a1 = g_adp[p1]; }
        #pragma unroll
        for (int nf = 0; nf < 4; nf++) {
            int cl = col_base + (nf << 3) + ((lane & 3) << 1);
            if (EPI == 0 && !ILV) {
                if (v0) *(float2*)(Out + (size_t)p0 * ldo + n0 + cl) =
                            make_float2(acc[mf][nf][0], acc[mf][nf][1]);
                if (v1) *(float2*)(Out + (size_t)p1 * ldo + n0 + cl) =
                            make_float2(acc[mf][nf][2], acc[mf][nf][3]);
            } else if (EPI <= 1) {
                #pragma unroll
                for (int q = 0; q < 2; q++) {
                    int nl = cl + q;
                    int co = n0 + (ILV ? pkf(nl) : nl);
                    if (EPI == 0) {
                        if (v0) Out[(size_t)p0 * ldo + co] = acc[mf][nf][q];
                        if (v1) Out[(size_t)p1 * ldo + co] = acc[mf][nf][2 + q];
                    } else {
                        if (v0) {
                            size_t i = (size_t)p0 * ldo + co;
                            float g = Out[i];
                            Out[i] = tf32f(acc[mf][nf][q] * g / (1.f + expf(-g)));
                        }
                        if (v1) {
                            size_t i = (size_t)p1 * ldo + co;
                            float g = Out[i];
                            Out[i] = tf32f(acc[mf][nf][2 + q] * g / (1.f + expf(-g)));
                        }
                    }
                }
            } else {
                #pragma unroll
                for (int q = 0; q < 2; q++) {
                    int n = cl + q;
                    int j = n & 31;
                    int slot = (n >> 4) & 1;
                    size_t d0, d1;
                    if (EPI == 2) {
                        size_t co = 2048 + ((n >> 5) << 5) + pkf(j);
                        d0 = (size_t)p0 * LDXG + co;
                        d1 = (size_t)p1 * LDXG + co;
                    } else {
                        size_t co = 1024 + pkf(j);
                        d0 = (size_t)p0 * LDGH + co;
                        d1 = (size_t)p1 * LDGH + co;
                    }
                    Out[d0] = (slot == a0) ? tf32f(acc[mf][nf][q])     : 0.f;
                    Out[d1] = (slot == a1) ? tf32f(acc[mf][nf][2 + q]) : 0.f;
                }
            }
        }
    }
}

// ---------------- combine ----------------
__global__ void combine_kernel(const float* __restrict__ rw, float* __restrict__ out) {
    int t = blockIdx.x;
    __shared__ int s_pos[TOPK];
    __shared__ float s_w[TOPK];
    if (threadIdx.x < TOPK) {
        s_pos[threadIdx.x] = g_pos[t*TOPK + threadIdx.x];
        s_w[threadIdx.x]   = rw[t*TOPK + threadIdx.x];
    }
    __syncthreads();
    for (int h = threadIdx.x * 4; h < HD; h += blockDim.x * 4) {
        float4 acc = make_float4(0.f, 0.f, 0.f, 0.f);
        #pragma unroll
        for (int k = 0; k < TOPK; k++) {
            const float4 v = *(const float4*)(g_O + (size_t)s_pos[k]*HD + h);
            float w = s_w[k];
            acc.x += w*v.x; acc.y += w*v.y; acc.z += w*v.z; acc.w += w*v.w;
        }
        *(float4*)(out + (size_t)t*HD + h) = acc;
    }
}

#define SM128 (2*(128*40 + 128*40)*4)
#define SM64  (2*(128*40 +  64*40)*4)
#define SM32  (2*(128*40 +  32*40)*4)

extern "C" void kernel_launch(void* const* d_in, const int* in_sizes, int n_in,
                              void* d_out, int out_size) {
    const float* hidden = (const float*)d_in[0];
    const int*   sel    = (const int*)  d_in[1];
    const float* rw     = (const float*)d_in[2];
    const int*   adp    = (const int*)  d_in[3];
    const float* Wg     = (const float*)d_in[4];
    const float* Ag     = (const float*)d_in[5];
    const float* Bg     = (const float*)d_in[6];
    const float* Wu     = (const float*)d_in[7];
    const float* Au     = (const float*)d_in[8];
    const float* Bu     = (const float*)d_in[9];
    const float* Wd     = (const float*)d_in[10];
    const float* Ad     = (const float*)d_in[11];
    const float* Bd     = (const float*)d_in[12];
    float* out = (float*)d_out;

    static bool init = false;
    if (!init) {
        cudaFuncSetAttribute(mm<128,0,0>, cudaFuncAttributeMaxDynamicSharedMemorySize, SM128);
        cudaFuncSetAttribute(mm<128,0,1>, cudaFuncAttributeMaxDynamicSharedMemorySize, SM128);
        cudaFuncSetAttribute(mm<128,1,1>, cudaFuncAttributeMaxDynamicSharedMemorySize, SM128);
        cudaFuncSetAttribute(mm<64,2,0>,  cudaFuncAttributeMaxDynamicSharedMemorySize, SM64);
        cudaFuncSetAttribute(mm<32,3,0>,  cudaFuncAttributeMaxDynamicSharedMemorySize, SM32);
        init = true;
    }

    float *Xg, *Gh, *O, *Wtg, *Wtu, *Wtd, *Azt, *Adt;
    cudaGetSymbolAddress((void**)&Xg,  g_Xg);
    cudaGetSymbolAddress((void**)&Gh,  g_Gh);
    cudaGetSymbolAddress((void**)&O,   g_O);
    cudaGetSymbolAddress((void**)&Wtg, g_Wtg);
    cudaGetSymbolAddress((void**)&Wtu, g_Wtu);
    cudaGetSymbolAddress((void**)&Wtd, g_Wtd);
    cudaGetSymbolAddress((void**)&Azt, g_Azt);
    cudaGetSymbolAddress((void**)&Adt, g_Adt);

    routing_kernel<<<1, 1024>>>(sel, adp);

    // pre-passes
    xconv<<<TE, 256>>>(hidden);
    wconv<<<dim3(ID/128, HD/32 + 1, NE), 256>>>(Wg, Bg, Wtg, HD, ID, KRGU);
    wconv<<<dim3(ID/128, HD/32 + 1, NE), 256>>>(Wu, Bu, Wtu, HD, ID, KRGU);
    wconv<<<dim3(HD/128, ID/32 + 1, NE), 256>>>(Wd, Bd, Wtd, ID, HD, KRD);
    aconv<<<dim3(NE, 3), 256>>>(Ag, Au, Ad);

    // Z(gate|up) -> Xg cols [2048,2112)
    mm<64,2,0><<<dim3(1, MAXT), 256, SM64>>>(Xg, LDXG, Azt, HD, 64, 64, 64, 0, Xg, 0);
    // gate -> Gh (fp32, interleaved cols)
    mm<128,0,1><<<dim3(ID/128, MAXT), 256, SM128>>>(Xg, LDXG, Wtg, KRGU, ID, 64, 65, 2048, Gh, LDGH);
    // up: Gh = tf32(silu(gate) * up), interleaved cols
    mm<128,1,1><<<dim3(ID/128, MAXT), 256, SM128>>>(Xg, LDXG, Wtu, KRGU, ID, 64, 65, 2080, Gh, LDGH);
    // Z(down) -> Gh cols [1024,1056)
    mm<32,3,0><<<dim3(1, MAXT), 256, SM32>>>(Gh, LDGH, Adt, ID, 32, 32, 32, 0, Gh, 0);
    // down -> O (natural cols)
    mm<128,0,0><<<dim3(HD/128, MAXT), 256, SM128>>>(Gh, LDGH, Wtd, KRD, HD, 32, 33, 1024, O, HD);

    combine_kernel<<<NT, 256>>>(rw, out);
}

// round 9
// speedup vs baseline: 2.0540x; 1.6075x over previous
#include <cuda_runtime.h>
#include <cuda_fp16.h>
#include <cstdint>
#include <math.h>

#define NE 32
#define TOPK 8
#define HD 2048
#define ID 1024
#define NT 4096
#define TE (NT*TOPK)
#define MAXT 288

#define LDXG 2112     // Xg row: 2048 X | 32 Zg | 32 Zu   (half, pair-interleaved)
#define LDGH 1056     // Gh row: 1024 h | 32 Zd           (half, pair-interleaved)
#define KRGU 2080     // Wt gate/up row: 2048 W + 32 loraB
#define KRD  1056     // Wt down row:    1024 W + 32 loraB

__device__ int g_cnt[NE], g_off[NE];
__device__ int g_tok[TE], g_adp[TE], g_pos[TE];
__device__ int g_te[MAXT], g_tm[MAXT], g_nt;
__device__ __half g_Xg[(size_t)TE*LDXG];
__device__ __half g_Gh[(size_t)TE*LDGH];
__device__ float  g_Gt[(size_t)TE*ID];     // gate, fp32 (silu precision)
__device__ float  g_O [(size_t)TE*HD];
__device__ __half g_Wtg[(size_t)NE*ID*KRGU];
__device__ __half g_Wtu[(size_t)NE*ID*KRGU];
__device__ __half g_Wtd[(size_t)NE*HD*KRD];
__device__ __half g_Azt[(size_t)NE*64*HD];
__device__ __half g_Adt[(size_t)NE*32*ID];

__device__ __forceinline__ uint32_t smem_u32(const void* p) {
    uint32_t a;
    asm("{ .reg .u64 t; cvta.to.shared.u64 t, %1; cvt.u32.u64 %0, t; }" : "=r"(a) : "l"(p));
    return a;
}
__device__ __forceinline__ void cpa16(uint32_t dst, const void* src) {
    asm volatile("cp.async.cg.shared.global [%0], [%1], 16;" :: "r"(dst), "l"(src) : "memory");
}
__device__ __forceinline__ void cpa_commit() { asm volatile("cp.async.commit_group;" ::: "memory"); }
__device__ __forceinline__ void cpa_wait1()  { asm volatile("cp.async.wait_group 1;" ::: "memory"); }
__device__ __forceinline__ void mma16(float* c, const uint32_t* a, const uint32_t* b) {
    asm volatile(
        "mma.sync.aligned.m16n8k16.row.col.f32.f16.f16.f32 "
        "{%0,%1,%2,%3}, {%4,%5,%6,%7}, {%8,%9}, {%0,%1,%2,%3};\n"
        : "+f"(c[0]), "+f"(c[1]), "+f"(c[2]), "+f"(c[3])
        : "r"(a[0]), "r"(a[1]), "r"(a[2]), "r"(a[3]), "r"(b[0]), "r"(b[1]));
}
// stored position of original k within each 16-group (pair interleave: pairs j, j+8 adjacent)
__device__ __forceinline__ int pkh(int k) {
    int op = (k >> 1) & 7;
    int sp = ((op & 3) << 1) | (op >> 2);
    return (k & ~15) + (sp << 1) + (k & 1);
}
// for even column cl: stored index of the (cl, cl+1) half2
__device__ __forceinline__ int shp(int cl) {
    int op = (cl >> 1) & 7;
    int sp = ((op & 3) << 1) | (op >> 2);
    return (cl & ~15) + (sp << 1);
}

// ---------------- routing ----------------
__global__ void routing_kernel(const int* __restrict__ sel, const int* __restrict__ adp) {
    __shared__ int s_cnt[NE], s_cur[NE];
    int tid = threadIdx.x;
    if (tid < NE) s_cnt[tid] = 0;
    __syncthreads();
    for (int i = tid; i < TE; i += blockDim.x) atomicAdd(&s_cnt[sel[i]], 1);
    __syncthreads();
    if (tid == 0) {
        int acc = 0, idx = 0;
        for (int e = 0; e < NE; e++) {
            int c = s_cnt[e];
            g_cnt[e] = c; g_off[e] = acc; s_cur[e] = acc; acc += c;
            for (int i = 0; i < (c + 127) >> 7; i++) { g_te[idx] = e; g_tm[idx] = i; idx++; }
        }
        g_nt = idx;
    }
    __syncthreads();
    for (int i = tid; i < TE; i += blockDim.x) {
        int e = sel[i];
        int pos = atomicAdd(&s_cur[e], 1);
        int t = i >> 3;
        g_tok[pos] = t; g_adp[pos] = adp[t]; g_pos[i] = pos;
    }
}

// ---------------- X pre-pass: gather + half + pair-interleave ----------------
__global__ void xconv(const float* __restrict__ hidden) {
    int p = blockIdx.x, t = threadIdx.x;
    int s0 = t << 3;                       // 8 stored halfs per thread
    int base = s0 & ~15;
    int lo = base + ((t & 1) << 2);
    const float* src = hidden + (size_t)g_tok[p] * HD;
    float4 a = *(const float4*)(src + lo);
    float4 b = *(const float4*)(src + lo + 8);
    __half2 o[4];
    o[0] = __halves2half2(__float2half_rn(a.x), __float2half_rn(a.y));
    o[1] = __halves2half2(__float2half_rn(b.x), __float2half_rn(b.y));
    o[2] = __halves2half2(__float2half_rn(a.z), __float2half_rn(a.w));
    o[3] = __halves2half2(__float2half_rn(b.z), __float2half_rn(b.w));
    *(uint4*)(g_Xg + (size_t)p * LDXG + s0) = *(uint4*)o;
}

// ---------------- W pre-pass: transpose + half + interleave + loraB rows ----------------
__global__ void wconv(const float* __restrict__ W, const float* __restrict__ B,
                      __half* __restrict__ Wt, int K, int N, int KR)
{
    __shared__ float s[32][132];
    int e = blockIdx.z, ky = blockIdx.y, n0 = blockIdx.x << 7;
    int tid = threadIdx.x;
    int KCn = K >> 5;
    #pragma unroll
    for (int i = 0; i < 4; i++) {
        int u = tid + (i << 8);
        int kk = u >> 5, c = (u & 31) << 2;
        const float* src;
        if (ky < KCn) src = W + ((size_t)e * K + (ky << 5) + kk) * N + n0 + c;
        else          src = B + (((size_t)(kk >> 4) * NE + e) * 16 + (kk & 15)) * N + n0 + c;
        float4 v = *(const float4*)src;
        s[kk][c] = v.x; s[kk][c+1] = v.y; s[kk][c+2] = v.z; s[kk][c+3] = v.w;
    }
    __syncthreads();
    #pragma unroll
    for (int i = 0; i < 2; i++) {
        int u = tid + (i << 8);
        int n = u >> 2, c8 = (u & 3) << 3;   // 8 stored halfs
        __half h[8];
        #pragma unroll
        for (int q = 0; q < 8; q++) {
            int j = c8 + q;
            int grp = j & ~15, w16 = j & 15;
            int sp = w16 >> 1, ee = w16 & 1;
            int op = ((sp & 1) << 2) | (sp >> 1);
            int k = grp + (op << 1) + ee;
            h[q] = __float2half_rn(s[k][n]);
        }
        *(uint4*)(Wt + ((size_t)e * N + n0 + n) * KR + (ky << 5) + c8) = *(uint4*)h;
    }
}

// ---------------- loraA pre-pass ----------------
__global__ void aconv(const float* __restrict__ Ag, const float* __restrict__ Au,
                      const float* __restrict__ Ad)
{
    int e = blockIdx.x, which = blockIdx.y, tid = threadIdx.x;
    int K = (which == 2) ? ID : HD;
    const float* A = (which == 0) ? Ag : (which == 1) ? Au : Ad;
    for (int u = tid; u < (K << 5); u += 256) {
        int n = u >> ((which == 2) ? 10 : 11);
        int k = u & (K - 1);
        int a = n >> 4, r = n & 15;
        __half v = __float2half_rn(__ldg(A + (((size_t)a * NE + e) * K + k) * 16 + r));
        int pk = pkh(k);
        if (which == 2) g_Adt[((size_t)e * 32 + n) * ID + pk] = v;
        else            g_Azt[((size_t)e * 64 + (which << 5) + n) * HD + pk] = v;
    }
}

// ---------------- unified fp16 tensor-core grouped GEMM ----------------
// EPI 0: plain fp32 store; 1: h=silu(Gt)*acc -> half interleaved; 2: masked Zgu->Xg; 3: masked Zd->Gh
template<int N_, int EPI>
__global__ __launch_bounds__(256, 2)
void mm(const __half* __restrict__ X, int ldx,
        const __half* __restrict__ Wt, int KR, int NWT,
        int KC, int KT, int zbase,
        void* __restrict__ OutV, int ldo, const float* __restrict__ Gt)
{
    if ((int)blockIdx.y >= g_nt) return;
    const int e   = g_te[blockIdx.y];
    const int m0  = g_tm[blockIdx.y] << 7;
    const int cnt = g_cnt[e], off = g_off[e];
    const int n0  = blockIdx.x * N_;
    const int tid = threadIdx.x, lane = tid & 31, wid = tid >> 5;
    constexpr int MW = 256 / N_;
    constexpr int MF = N_ / 32;
    constexpr int XS = 128 * 48;      // halfs per X stage (stride 48 halfs = 96B)
    constexpr int WS = N_ * 48;
    constexpr int STG = XS + WS;
    const int row_base = (wid % MW) * (128 / MW);
    const int col_base = (wid / MW) * 32;

    extern __shared__ __half sm[];
    const uint32_t smb = smem_u32(sm);
    const __half* Wte = Wt + ((size_t)e * NWT + n0) * KR;

    auto issue = [&](int kc, int buf) {
        const int xoff = (kc < KC) ? (kc << 5) : zbase;
        #pragma unroll
        for (int i = 0; i < 2; i++) {
            int u = tid + (i << 8);
            int r = u >> 2, c8 = (u & 3) << 3;
            int p = off + min(m0 + r, cnt - 1);
            cpa16(smb + ((buf * STG + r * 48 + c8) << 1),
                  X + (size_t)p * ldx + xoff + c8);
        }
        const int kr = kc << 5;
        #pragma unroll
        for (int i = 0; i < (N_ > 64 ? 2 : 1); i++) {
            int u = tid + (i << 8);
            if (N_ >= 64 || u < (N_ << 2)) {
                int n = u >> 2, c8 = (u & 3) << 3;
                if (N_ == 64 || n < N_)
                    cpa16(smb + ((buf * STG + XS + n * 48 + c8) << 1),
                          Wte + (size_t)n * KR + kr + c8);
            }
        }
    };

    float acc[MF][4][4];
    #pragma unroll
    for (int i = 0; i < MF; i++)
        #pragma unroll
        for (int j = 0; j < 4; j++) { acc[i][j][0]=0.f; acc[i][j][1]=0.f; acc[i][j][2]=0.f; acc[i][j][3]=0.f; }

    issue(0, 0); cpa_commit();
    if (KT > 1) issue(1, 1);
    cpa_commit();

    for (int kc = 0; kc < KT; kc++) {
        cpa_wait1();
        __syncthreads();
        const int buf = kc & 1;
        const __half* xs = sm + buf * STG;
        const __half* ws = sm + buf * STG + XS;
        #pragma unroll
        for (int ks = 0; ks < 2; ks++) {
            const int ko = (ks << 4) + ((lane & 3) << 2);
            uint32_t A[MF][4];
            #pragma unroll
            for (int mf = 0; mf < MF; mf++) {
                int r0 = row_base + (mf << 4) + (lane >> 2);
                uint2 x = *(const uint2*)&xs[r0 * 48 + ko];
                uint2 y = *(const uint2*)&xs[(r0 + 8) * 48 + ko];
                A[mf][0] = x.x; A[mf][1] = y.x; A[mf][2] = x.y; A[mf][3] = y.y;
            }
            uint32_t B[4][2];
            #pragma unroll
            for (int nf = 0; nf < 4; nf++) {
                int cb = col_base + (nf << 3) + (lane >> 2);
                uint2 z = *(const uint2*)&ws[cb * 48 + ko];
                B[nf][0] = z.x; B[nf][1] = z.y;
            }
            #pragma unroll
            for (int mf = 0; mf < MF; mf++)
                #pragma unroll
                for (int nf = 0; nf < 4; nf++)
                    mma16(acc[mf][nf], A[mf], B[nf]);
        }
        __syncthreads();
        if (kc + 2 < KT) issue(kc + 2, buf);
        cpa_commit();
    }

    // ---------------- epilogue ----------------
    #pragma unroll
    for (int mf = 0; mf < MF; mf++) {
        int rl0 = row_base + (mf << 4) + (lane >> 2);
        int rl1 = rl0 + 8;
        bool v0 = (m0 + rl0) < cnt, v1 = (m0 + rl1) < cnt;
        int p0 = off + min(m0 + rl0, cnt - 1);
        int p1 = off + min(m0 + rl1, cnt - 1);
        int a0 = 0, a1 = 0;
        if (EPI >= 2) { a0 = g_adp[p0]; a1 = g_adp[p1]; }
        #pragma unroll
        for (int nf = 0; nf < 4; nf++) {
            int cl = col_base + (nf << 3) + ((lane & 3) << 1);
            if (EPI == 0) {
                float* Out = (float*)OutV;
                if (v0) *(float2*)(Out + (size_t)p0 * ldo + n0 + cl) =
                            make_float2(acc[mf][nf][0], acc[mf][nf][1]);
                if (v1) *(float2*)(Out + (size_t)p1 * ldo + n0 + cl) =
                            make_float2(acc[mf][nf][2], acc[mf][nf][3]);
            } else if (EPI == 1) {
                __half* Out = (__half*)OutV;
                int co = n0 + shp(cl);
                if (v0) {
                    float gx = Gt[(size_t)p0 * ID + n0 + cl];
                    float gy = Gt[(size_t)p0 * ID + n0 + cl + 1];
                    float hx = acc[mf][nf][0] * gx / (1.f + expf(-gx));
                    float hy = acc[mf][nf][1] * gy / (1.f + expf(-gy));
                    *(__half2*)(Out + (size_t)p0 * ldo + co) =
                        __halves2half2(__float2half_rn(hx), __float2half_rn(hy));
                }
                if (v1) {
                    float gx = Gt[(size_t)p1 * ID + n0 + cl];
                    float gy = Gt[(size_t)p1 * ID + n0 + cl + 1];
                    float hx = acc[mf][nf][2] * gx / (1.f + expf(-gx));
                    float hy = acc[mf][nf][3] * gy / (1.f + expf(-gy));
                    *(__half2*)(Out + (size_t)p1 * ldo + co) =
                        __halves2half2(__float2half_rn(hx), __float2half_rn(hy));
                }
            } else {
                __half* Out = (__half*)OutV;
                int n = cl;
                int slot, co;
                if (EPI == 2) {
                    int w = n & 31;
                    slot = (w >> 4) & 1;
                    co = 2048 + ((n >> 5) << 5) + shp(w);
                } else {
                    slot = (n >> 4) & 1;
                    co = 1024 + shp(n);
                }
                __half2 z0 = (slot == a0)
                    ? __halves2half2(__float2half_rn(acc[mf][nf][0]), __float2half_rn(acc[mf][nf][1]))
                    : __halves2half2(__float2half_rn(0.f), __float2half_rn(0.f));
                __half2 z1 = (slot == a1)
                    ? __halves2half2(__float2half_rn(acc[mf][nf][2]), __float2half_rn(acc[mf][nf][3]))
                    : __halves2half2(__float2half_rn(0.f), __float2half_rn(0.f));
                *(__half2*)(Out + (size_t)p0 * ldo + co) = z0;
                *(__half2*)(Out + (size_t)p1 * ldo + co) = z1;
            }
        }
    }
}

// ---------------- combine ----------------
__global__ void combine_kernel(const float* __restrict__ rw, float* __restrict__ out) {
    int t = blockIdx.x;
    __shared__ int s_pos[TOPK];
    __shared__ float s_w[TOPK];
    if (threadIdx.x < TOPK) {
        s_pos[threadIdx.x] = g_pos[t*TOPK + threadIdx.x];
        s_w[threadIdx.x]   = rw[t*TOPK + threadIdx.x];
    }
    __syncthreads();
    for (int h = threadIdx.x * 4; h < HD; h += blockDim.x * 4) {
        float4 acc = make_float4(0.f, 0.f, 0.f, 0.f);
        #pragma unroll
        for (int k = 0; k < TOPK; k++) {
            const float4 v = *(const float4*)(g_O + (size_t)s_pos[k]*HD + h);
            float w = s_w[k];
            acc.x += w*v.x; acc.y += w*v.y; acc.z += w*v.z; acc.w += w*v.w;
        }
        *(float4*)(out + (size_t)t*HD + h) = acc;
    }
}

#define SM128 (2*(128*48 + 128*48)*2)
#define SM64  (2*(128*48 +  64*48)*2)
#define SM32  (2*(128*48 +  32*48)*2)

extern "C" void kernel_launch(void* const* d_in, const int* in_sizes, int n_in,
                              void* d_out, int out_size) {
    const float* hidden = (const float*)d_in[0];
    const int*   sel    = (const int*)  d_in[1];
    const float* rw     = (const float*)d_in[2];
    const int*   adp    = (const int*)  d_in[3];
    const float* Wg     = (const float*)d_in[4];
    const float* Ag     = (const float*)d_in[5];
    const float* Bg     = (const float*)d_in[6];
    const float* Wu     = (const float*)d_in[7];
    const float* Au     = (const float*)d_in[8];
    const float* Bu     = (const float*)d_in[9];
    const float* Wd     = (const float*)d_in[10];
    const float* Ad     = (const float*)d_in[11];
    const float* Bd     = (const float*)d_in[12];
    float* out = (float*)d_out;

    static bool init = false;
    if (!init) {
        cudaFuncSetAttribute(mm<128,0>, cudaFuncAttributeMaxDynamicSharedMemorySize, SM128);
        cudaFuncSetAttribute(mm<128,1>, cudaFuncAttributeMaxDynamicSharedMemorySize, SM128);
        cudaFuncSetAttribute(mm<64,2>,  cudaFuncAttributeMaxDynamicSharedMemorySize, SM64);
        cudaFuncSetAttribute(mm<32,3>,  cudaFuncAttributeMaxDynamicSharedMemorySize, SM32);
        init = true;
    }

    __half *Xg, *Gh, *Wtg, *Wtu, *Wtd, *Azt, *Adt;
    float *Gt, *O;
    cudaGetSymbolAddress((void**)&Xg,  g_Xg);
    cudaGetSymbolAddress((void**)&Gh,  g_Gh);
    cudaGetSymbolAddress((void**)&Gt,  g_Gt);
    cudaGetSymbolAddress((void**)&O,   g_O);
    cudaGetSymbolAddress((void**)&Wtg, g_Wtg);
    cudaGetSymbolAddress((void**)&Wtu, g_Wtu);
    cudaGetSymbolAddress((void**)&Wtd, g_Wtd);
    cudaGetSymbolAddress((void**)&Azt, g_Azt);
    cudaGetSymbolAddress((void**)&Adt, g_Adt);

    routing_kernel<<<1, 1024>>>(sel, adp);

    // pre-passes
    xconv<<<TE, 256>>>(hidden);
    wconv<<<dim3(ID/128, HD/32 + 1, NE), 256>>>(Wg, Bg, Wtg, HD, ID, KRGU);
    wconv<<<dim3(ID/128, HD/32 + 1, NE), 256>>>(Wu, Bu, Wtu, HD, ID, KRGU);
    wconv<<<dim3(HD/128, ID/32 + 1, NE), 256>>>(Wd, Bd, Wtd, ID, HD, KRD);
    aconv<<<dim3(NE, 3), 256>>>(Ag, Au, Ad);

    // Z(gate|up) -> Xg cols [2048,2112)
    mm<64,2><<<dim3(1, MAXT), 256, SM64>>>(Xg, LDXG, Azt, HD, 64, 64, 64, 0, Xg, LDXG, nullptr);
    // gate -> Gt (fp32, natural)
    mm<128,0><<<dim3(ID/128, MAXT), 256, SM128>>>(Xg, LDXG, Wtg, KRGU, ID, 64, 65, 2048, Gt, ID, nullptr);
    // up: Gh = half(silu(Gt) * up), interleaved cols
    mm<128,1><<<dim3(ID/128, MAXT), 256, SM128>>>(Xg, LDXG, Wtu, KRGU, ID, 64, 65, 2080, Gh, LDGH, Gt);
    // Z(down) -> Gh cols [1024,1056)
    mm<32,3><<<dim3(1, MAXT), 256, SM32>>>(Gh, LDGH, Adt, ID, 32, 32, 32, 0, Gh, LDGH, nullptr);
    // down -> O (fp32, natural)
    mm<128,0><<<dim3(HD/128, MAXT), 256, SM128>>>(Gh, LDGH, Wtd, KRD, HD, 32, 33, 1024, O, HD, nullptr);

    combine_kernel<<<NT, 256>>>(rw, out);
}

// round 10
// speedup vs baseline: 2.2778x; 1.1089x over previous
#include <cuda_runtime.h>
#include <cuda_fp16.h>
#include <cstdint>
#include <math.h>

#define NE 32
#define TOPK 8
#define HD 2048
#define ID 1024
#define NT 4096
#define TE (NT*TOPK)
#define MAXT 288

#define LDXG 2112     // Xg row: 2048 X | 32 Zg | 32 Zu  (half, pair-interleaved k)
#define LDGH 1056     // Gh row: 1024 h | 32 Zd
#define KRGU 2112     // Wtg/Wtu row: 2048 W | 32 loraB(gate) | 32 zero   (up: zero|loraB)
#define KRD  1056     // Wtd row: 1024 W | 32 loraB

__device__ int g_cnt[NE], g_off[NE];
__device__ int g_tok[TE], g_adp[TE], g_pos[TE];
__device__ int g_te[MAXT], g_tm[MAXT], g_nt;
__device__ __half g_Xg[(size_t)TE*LDXG];
__device__ __half g_Gh[(size_t)TE*LDGH];
__device__ float  g_O [(size_t)TE*HD];
__device__ __half g_Wtg[(size_t)NE*ID*KRGU];
__device__ __half g_Wtu[(size_t)NE*ID*KRGU];
__device__ __half g_Wtd[(size_t)NE*HD*KRD];
__device__ __half g_Azt[(size_t)NE*64*HD];
__device__ __half g_Adt[(size_t)NE*32*ID];

__device__ __forceinline__ uint32_t smem_u32(const void* p) {
    uint32_t a;
    asm("{ .reg .u64 t; cvta.to.shared.u64 t, %1; cvt.u32.u64 %0, t; }" : "=r"(a) : "l"(p));
    return a;
}
__device__ __forceinline__ void cpa16(uint32_t dst, const void* src) {
    asm volatile("cp.async.cg.shared.global [%0], [%1], 16;" :: "r"(dst), "l"(src) : "memory");
}
__device__ __forceinline__ void cpa_commit() { asm volatile("cp.async.commit_group;" ::: "memory"); }
__device__ __forceinline__ void cpa_wait1()  { asm volatile("cp.async.wait_group 1;" ::: "memory"); }
__device__ __forceinline__ void mma16(float* c, const uint32_t* a, const uint32_t* b) {
    asm volatile(
        "mma.sync.aligned.m16n8k16.row.col.f32.f16.f16.f32 "
        "{%0,%1,%2,%3}, {%4,%5,%6,%7}, {%8,%9}, {%0,%1,%2,%3};\n"
        : "+f"(c[0]), "+f"(c[1]), "+f"(c[2]), "+f"(c[3])
        : "r"(a[0]), "r"(a[1]), "r"(a[2]), "r"(a[3]), "r"(b[0]), "r"(b[1]));
}
// stored position of original k within each 16-group (pair interleave)
__device__ __forceinline__ int pkh(int k) {
    int op = (k >> 1) & 7;
    int sp = ((op & 3) << 1) | (op >> 2);
    return (k & ~15) + (sp << 1) + (k & 1);
}
// stored index of the (cl, cl+1) half2, cl even
__device__ __forceinline__ int shp(int cl) {
    int op = (cl >> 1) & 7;
    int sp = ((op & 3) << 1) | (op >> 2);
    return (cl & ~15) + (sp << 1);
}

// ---------------- routing ----------------
__global__ void routing_kernel(const int* __restrict__ sel, const int* __restrict__ adp) {
    __shared__ int s_cnt[NE], s_cur[NE];
    int tid = threadIdx.x;
    if (tid < NE) s_cnt[tid] = 0;
    __syncthreads();
    for (int i = tid; i < TE; i += blockDim.x) atomicAdd(&s_cnt[sel[i]], 1);
    __syncthreads();
    if (tid == 0) {
        int acc = 0, idx = 0;
        for (int e = 0; e < NE; e++) {
            int c = s_cnt[e];
            g_cnt[e] = c; g_off[e] = acc; s_cur[e] = acc; acc += c;
            for (int i = 0; i < (c + 127) >> 7; i++) { g_te[idx] = e; g_tm[idx] = i; idx++; }
        }
        g_nt = idx;
    }
    __syncthreads();
    for (int i = tid; i < TE; i += blockDim.x) {
        int e = sel[i];
        int pos = atomicAdd(&s_cur[e], 1);
        int t = i >> 3;
        g_tok[pos] = t; g_adp[pos] = adp[t]; g_pos[i] = pos;
    }
}

// ---------------- X pre-pass ----------------
__global__ void xconv(const float* __restrict__ hidden) {
    int p = blockIdx.x, t = threadIdx.x;
    int s0 = t << 3;
    int lo = (s0 & ~15) + ((t & 1) << 2);
    const float* src = hidden + (size_t)g_tok[p] * HD;
    float4 a = *(const float4*)(src + lo);
    float4 b = *(const float4*)(src + lo + 8);
    __half2 o[4];
    o[0] = __halves2half2(__float2half_rn(a.x), __float2half_rn(a.y));
    o[1] = __halves2half2(__float2half_rn(b.x), __float2half_rn(b.y));
    o[2] = __halves2half2(__float2half_rn(a.z), __float2half_rn(a.w));
    o[3] = __halves2half2(__float2half_rn(b.z), __float2half_rn(b.w));
    *(uint4*)(g_Xg + (size_t)p * LDXG + s0) = *(uint4*)o;
}

// ---------------- W pre-pass: transpose + half + interleave; lora block at kyl, zeros elsewhere past K ----------------
__global__ void wconv(const float* __restrict__ W, const float* __restrict__ B,
                      __half* __restrict__ Wt, int K, int N, int KR, int kyl)
{
    __shared__ float s[32][132];
    int e = blockIdx.z, ky = blockIdx.y, n0 = blockIdx.x << 7;
    int tid = threadIdx.x;
    int KCn = K >> 5;
    #pragma unroll
    for (int i = 0; i < 4; i++) {
        int u = tid + (i << 8);
        int kk = u >> 5, c = (u & 31) << 2;
        float4 v = make_float4(0.f, 0.f, 0.f, 0.f);
        if (ky < KCn)
            v = *(const float4*)(W + ((size_t)e * K + (ky << 5) + kk) * N + n0 + c);
        else if (ky == kyl)
            v = *(const float4*)(B + (((size_t)(kk >> 4) * NE + e) * 16 + (kk & 15)) * N + n0 + c);
        s[kk][c] = v.x; s[kk][c+1] = v.y; s[kk][c+2] = v.z; s[kk][c+3] = v.w;
    }
    __syncthreads();
    #pragma unroll
    for (int i = 0; i < 2; i++) {
        int u = tid + (i << 8);
        int n = u >> 2, c8 = (u & 3) << 3;
        __half h[8];
        #pragma unroll
        for (int q = 0; q < 8; q++) {
            int j = c8 + q;
            int grp = j & ~15, w16 = j & 15;
            int sp = w16 >> 1, ee = w16 & 1;
            int op = ((sp & 1) << 2) | (sp >> 1);
            int k = grp + (op << 1) + ee;
            h[q] = __float2half_rn(s[k][n]);
        }
        *(uint4*)(Wt + ((size_t)e * N + n0 + n) * KR + (ky << 5) + c8) = *(uint4*)h;
    }
}

// ---------------- loraA pre-pass ----------------
__global__ void aconv(const float* __restrict__ Ag, const float* __restrict__ Au,
                      const float* __restrict__ Ad)
{
    int e = blockIdx.x, which = blockIdx.y, tid = threadIdx.x;
    int K = (which == 2) ? ID : HD;
    const float* A = (which == 0) ? Ag : (which == 1) ? Au : Ad;
    for (int u = tid; u < (K << 5); u += 256) {
        int n = u >> ((which == 2) ? 10 : 11);
        int k = u & (K - 1);
        int a = n >> 4, r = n & 15;
        __half v = __float2half_rn(__ldg(A + (((size_t)a * NE + e) * K + k) * 16 + r));
        int pk = pkh(k);
        if (which == 2) g_Adt[((size_t)e * 32 + n) * ID + pk] = v;
        else            g_Azt[((size_t)e * 64 + (which << 5) + n) * HD + pk] = v;
    }
}

// ---------------- unified fp16 grouped GEMM, 3-stage cp.async, 1 sync/chunk ----------------
// EPI 0: plain fp32 store (down)
// EPI 1: fused gate+up — B rows interleave 8-col gate/up blocks; h=u*silu(g) in-register -> Gh
// EPI 2: masked Zgu -> Xg cols 2048+ ; EPI 3: masked Zd -> Gh cols 1024+
template<int N_, int EPI>
__global__ __launch_bounds__(256, 2)
void mm(const __half* __restrict__ X, int ldx,
        const __half* __restrict__ W0, const __half* __restrict__ W1,
        int KR, int NWT, int KT,
        void* __restrict__ OutV, int ldo)
{
    if ((int)blockIdx.y >= g_nt) return;
    const int e   = g_te[blockIdx.y];
    const int m0  = g_tm[blockIdx.y] << 7;
    const int cnt = g_cnt[e], off = g_off[e];
    const int n0  = blockIdx.x * ((EPI == 1) ? (N_ / 2) : N_);
    const int tid = threadIdx.x, lane = tid & 31, wid = tid >> 5;
    constexpr int MW = 256 / N_;
    constexpr int MF = N_ / 32;
    constexpr int XS = 128 * 48;
    constexpr int WS = N_ * 48;
    constexpr int STG = XS + WS;
    const int row_base = (wid % MW) * (128 / MW);
    const int col_base = (wid / MW) * 32;

    extern __shared__ __half sm[];
    const uint32_t smb = smem_u32(sm);
    const __half* W0e = W0 + (size_t)e * NWT * KR;
    const __half* W1e = (EPI == 1) ? (W1 + (size_t)e * NWT * KR) : W0;

    auto issue = [&](int kc, int buf) {
        const int ko = kc << 5;
        #pragma unroll
        for (int i = 0; i < 2; i++) {
            int u = tid + (i << 8);
            int r = u >> 2, c8 = (u & 3) << 3;
            int p = off + min(m0 + r, cnt - 1);
            cpa16(smb + ((buf * STG + r * 48 + c8) << 1), X + (size_t)p * ldx + ko + c8);
        }
        #pragma unroll
        for (int i = 0; i < (N_ >= 128 ? 2 : 1); i++) {
            int u = tid + (i << 8);
            if (N_ >= 64 || u < (N_ << 2)) {
                int n = u >> 2, c8 = (u & 3) << 3;
                const __half* src;
                if (EPI == 1) {
                    int a = n >> 3, pair = a >> 1, up = a & 1;
                    int srow = n0 + (pair << 3) + (n & 7);
                    src = (up ? W1e : W0e) + (size_t)srow * KR + ko + c8;
                } else {
                    src = W0e + (size_t)(n0 + n) * KR + ko + c8;
                }
                cpa16(smb + ((buf * STG + XS + n * 48 + c8) << 1), src);
            }
        }
    };

    float acc[MF][4][4];
    #pragma unroll
    for (int i = 0; i < MF; i++)
        #pragma unroll
        for (int j = 0; j < 4; j++) { acc[i][j][0]=0.f; acc[i][j][1]=0.f; acc[i][j][2]=0.f; acc[i][j][3]=0.f; }

    issue(0, 0); cpa_commit();
    issue(1, 1); cpa_commit();

    for (int kc = 0; kc < KT; kc++) {
        cpa_wait1();
        __syncthreads();
        if (kc + 2 < KT) issue(kc + 2, (kc + 2) % 3);
        cpa_commit();
        const __half* xs = sm + (kc % 3) * STG;
        const __half* ws = xs + XS;
        #pragma unroll
        for (int ks = 0; ks < 2; ks++) {
            const int ko2 = (ks << 4) + ((lane & 3) << 2);
            uint32_t A[MF][4];
            #pragma unroll
            for (int mf = 0; mf < MF; mf++) {
                int r0 = row_base + (mf << 4) + (lane >> 2);
                uint2 x = *(const uint2*)&xs[r0 * 48 + ko2];
                uint2 y = *(const uint2*)&xs[(r0 + 8) * 48 + ko2];
                A[mf][0] = x.x; A[mf][1] = y.x; A[mf][2] = x.y; A[mf][3] = y.y;
            }
            uint32_t B[4][2];
            #pragma unroll
            for (int nf = 0; nf < 4; nf++) {
                int cb = col_base + (nf << 3) + (lane >> 2);
                uint2 z = *(const uint2*)&ws[cb * 48 + ko2];
                B[nf][0] = z.x; B[nf][1] = z.y;
            }
            #pragma unroll
            for (int mf = 0; mf < MF; mf++)
                #pragma unroll
                for (int nf = 0; nf < 4; nf++)
                    mma16(acc[mf][nf], A[mf], B[nf]);
        }
    }

    // ---------------- epilogue ----------------
    const int wcol = wid / MW;
    #pragma unroll
    for (int mf = 0; mf < MF; mf++) {
        int rl0 = row_base + (mf << 4) + (lane >> 2);
        int rl1 = rl0 + 8;
        bool v0 = (m0 + rl0) < cnt, v1 = (m0 + rl1) < cnt;
        int p0 = off + min(m0 + rl0, cnt - 1);
        int p1 = off + min(m0 + rl1, cnt - 1);
        if (EPI == 0) {
            float* Out = (float*)OutV;
            #pragma unroll
            for (int nf = 0; nf < 4; nf++) {
                int cl = col_base + (nf << 3) + ((lane & 3) << 1);
                if (v0) *(float2*)(Out + (size_t)p0 * ldo + n0 + cl) =
                            make_float2(acc[mf][nf][0], acc[mf][nf][1]);
                if (v1) *(float2*)(Out + (size_t)p1 * ldo + n0 + cl) =
                            make_float2(acc[mf][nf][2], acc[mf][nf][3]);
            }
        } else if (EPI == 1) {
            __half* Out = (__half*)OutV;
            #pragma unroll
            for (int pi = 0; pi < 2; pi++) {
                int outc = n0 + ((wcol << 1) + pi) * 8 + ((lane & 3) << 1);
                int co = shp(outc);
                float g0 = acc[mf][2*pi][0],   g1 = acc[mf][2*pi][1];
                float u0 = acc[mf][2*pi+1][0], u1 = acc[mf][2*pi+1][1];
                float g2 = acc[mf][2*pi][2],   g3 = acc[mf][2*pi][3];
                float u2 = acc[mf][2*pi+1][2], u3 = acc[mf][2*pi+1][3];
                if (v0) {
                    float h0 = u0 * g0 / (1.f + expf(-g0));
                    float h1 = u1 * g1 / (1.f + expf(-g1));
                    *(__half2*)(Out + (size_t)p0 * ldo + co) =
                        __halves2half2(__float2half_rn(h0), __float2half_rn(h1));
                }
                if (v1) {
                    float h2 = u2 * g2 / (1.f + expf(-g2));
                    float h3 = u3 * g3 / (1.f + expf(-g3));
                    *(__half2*)(Out + (size_t)p1 * ldo + co) =
                        __halves2half2(__float2half_rn(h2), __float2half_rn(h3));
                }
            }
        } else {
            __half* Out = (__half*)OutV;
            int a0 = g_adp[p0], a1 = g_adp[p1];
            #pragma unroll
            for (int nf = 0; nf < 4; nf++) {
                int cl = col_base + (nf << 3) + ((lane & 3) << 1);
                int slot, co;
                if (EPI == 2) {
                    int w = cl & 31;
                    slot = (w >> 4) & 1;
                    co = 2048 + ((cl >> 5) << 5) + shp(w);
                } else {
                    slot = (cl >> 4) & 1;
                    co = 1024 + shp(cl);
                }
                __half2 z0 = (slot == a0)
                    ? __halves2half2(__float2half_rn(acc[mf][nf][0]), __float2half_rn(acc[mf][nf][1]))
                    : __halves2half2(__float2half_rn(0.f), __float2half_rn(0.f));
                __half2 z1 = (slot == a1)
                    ? __halves2half2(__float2half_rn(acc[mf][nf][2]), __float2half_rn(acc[mf][nf][3]))
                    : __halves2half2(__float2half_rn(0.f), __float2half_rn(0.f));
                *(__half2*)(Out + (size_t)p0 * ldo + co) = z0;
                *(__half2*)(Out + (size_t)p1 * ldo + co) = z1;
            }
        }
    }
}

// ---------------- combine ----------------
__global__ void combine_kernel(const float* __restrict__ rw, float* __restrict__ out) {
    int t = blockIdx.x;
    __shared__ int s_pos[TOPK];
    __shared__ float s_w[TOPK];
    if (threadIdx.x < TOPK) {
        s_pos[threadIdx.x] = g_pos[t*TOPK + threadIdx.x];
        s_w[threadIdx.x]   = rw[t*TOPK + threadIdx.x];
    }
    __syncthreads();
    for (int h = threadIdx.x * 4; h < HD; h += blockDim.x * 4) {
        float4 acc = make_float4(0.f, 0.f, 0.f, 0.f);
        #pragma unroll
        for (int k = 0; k < TOPK; k++) {
            const float4 v = *(const float4*)(g_O + (size_t)s_pos[k]*HD + h);
            float w = s_w[k];
            acc.x += w*v.x; acc.y += w*v.y; acc.z += w*v.z; acc.w += w*v.w;
        }
        *(float4*)(out + (size_t)t*HD + h) = acc;
    }
}

#define SM128 (3*(128*48 + 128*48)*2)
#define SM64  (3*(128*48 +  64*48)*2)
#define SM32  (3*(128*48 +  32*48)*2)

extern "C" void kernel_launch(void* const* d_in, const int* in_sizes, int n_in,
                              void* d_out, int out_size) {
    const float* hidden = (const float*)d_in[0];
    const int*   sel    = (const int*)  d_in[1];
    const float* rw     = (const float*)d_in[2];
    const int*   adp    = (const int*)  d_in[3];
    const float* Wg     = (const float*)d_in[4];
    const float* Ag     = (const float*)d_in[5];
    const float* Bg     = (const float*)d_in[6];
    const float* Wu     = (const float*)d_in[7];
    const float* Au     = (const float*)d_in[8];
    const float* Bu     = (const float*)d_in[9];
    const float* Wd     = (const float*)d_in[10];
    const float* Ad     = (const float*)d_in[11];
    const float* Bd     = (const float*)d_in[12];
    float* out = (float*)d_out;

    static bool init = false;
    if (!init) {
        cudaFuncSetAttribute(mm<128,0>, cudaFuncAttributeMaxDynamicSharedMemorySize, SM128);
        cudaFuncSetAttribute(mm<128,1>, cudaFuncAttributeMaxDynamicSharedMemorySize, SM128);
        cudaFuncSetAttribute(mm<64,2>,  cudaFuncAttributeMaxDynamicSharedMemorySize, SM64);
        cudaFuncSetAttribute(mm<32,3>,  cudaFuncAttributeMaxDynamicSharedMemorySize, SM32);
        init = true;
    }

    __half *Xg, *Gh, *Wtg, *Wtu, *Wtd, *Azt, *Adt;
    float *O;
    cudaGetSymbolAddress((void**)&Xg,  g_Xg);
    cudaGetSymbolAddress((void**)&Gh,  g_Gh);
    cudaGetSymbolAddress((void**)&O,   g_O);
    cudaGetSymbolAddress((void**)&Wtg, g_Wtg);
    cudaGetSymbolAddress((void**)&Wtu, g_Wtu);
    cudaGetSymbolAddress((void**)&Wtd, g_Wtd);
    cudaGetSymbolAddress((void**)&Azt, g_Azt);
    cudaGetSymbolAddress((void**)&Adt, g_Adt);

    routing_kernel<<<1, 1024>>>(sel, adp);

    // pre-passes
    xconv<<<TE, 256>>>(hidden);
    wconv<<<dim3(ID/128, KRGU/32, NE), 256>>>(Wg, Bg, Wtg, HD, ID, KRGU, 64);
    wconv<<<dim3(ID/128, KRGU/32, NE), 256>>>(Wu, Bu, Wtu, HD, ID, KRGU, 65);
    wconv<<<dim3(HD/128, KRD/32, NE), 256>>>(Wd, Bd, Wtd, ID, HD, KRD, 32);
    aconv<<<dim3(NE, 3), 256>>>(Ag, Au, Ad);

    // Z(gate|up) -> Xg cols [2048,2112)
    mm<64,2><<<dim3(1, MAXT), 256, SM64>>>(Xg, LDXG, Azt, nullptr, HD, 64, 64, Xg, LDXG);
    // fused gate+up -> Gh (h = silu(g)*u, half, interleaved)
    mm<128,1><<<dim3(ID/64, MAXT), 256, SM128>>>(Xg, LDXG, Wtg, Wtu, KRGU, ID, 66, Gh, LDGH);
    // Z(down) -> Gh cols [1024,1056)
    mm<32,3><<<dim3(1, MAXT), 256, SM32>>>(Gh, LDGH, Adt, nullptr, ID, 32, 32, Gh, LDGH);
    // down -> O (fp32)
    mm<128,0><<<dim3(HD/128, MAXT), 256, SM128>>>(Gh, LDGH, Wtd, nullptr, KRD, HD, 33, O, HD);

    combine_kernel<<<NT, 256>>>(rw, out);
}

// round 12
// speedup vs baseline: 2.6718x; 1.1730x over previous
#include <cuda_runtime.h>
#include <cuda_fp16.h>
#include <cstdint>
#include <math.h>

#define NE 32
#define TOPK 8
#define HD 2048
#define ID 1024
#define NT 4096
#define TE (NT*TOPK)
#define MAXT 288
#define PTE (MAXT*128)      // padded position space (128-aligned expert groups)

#define KGX 132             // Xg kgroups: 128 X | 2 Zg | 2 Zu   (16 cols each)
#define KGH 66              // Gh kgroups: 64 h | 2 Zd

__device__ int g_cnt[NE], g_off[NE];
__device__ int g_tok[PTE], g_adp[PTE], g_pos[TE];
__device__ int g_te[MAXT], g_tm[MAXT], g_nt;
__device__ __half g_Xg[(size_t)PTE*16*KGX/16*16];      // PTE*2112, fragment units
__device__ __half g_Gh[(size_t)PTE*16*KGH/16*16];      // PTE*1056
__device__ float  g_O [(size_t)PTE*HD];
__device__ __half g_Wgu[(size_t)NE*128*KGX*256];       // fused gate|up image
__device__ __half g_Wd [(size_t)NE*128*KGH*256];
__device__ __half g_Azt[(size_t)NE*4*128*256];
__device__ __half g_Adt[(size_t)NE*2*64*256];

__device__ __forceinline__ uint32_t smem_u32(const void* p) {
    uint32_t a;
    asm("{ .reg .u64 t; cvta.to.shared.u64 t, %1; cvt.u32.u64 %0, t; }" : "=r"(a) : "l"(p));
    return a;
}
__device__ __forceinline__ void cpa16(uint32_t dst, const void* src) {
    asm volatile("cp.async.cg.shared.global [%0], [%1], 16;" :: "r"(dst), "l"(src) : "memory");
}
__device__ __forceinline__ void cpa_commit() { asm volatile("cp.async.commit_group;" ::: "memory"); }
__device__ __forceinline__ void cpa_wait1()  { asm volatile("cp.async.wait_group 1;" ::: "memory"); }
__device__ __forceinline__ void mma16(float* c, const uint32_t* a, const uint32_t* b) {
    asm volatile(
        "mma.sync.aligned.m16n8k16.row.col.f32.f16.f16.f32 "
        "{%0,%1,%2,%3}, {%4,%5,%6,%7}, {%8,%9}, {%0,%1,%2,%3};\n"
        : "+f"(c[0]), "+f"(c[1]), "+f"(c[2]), "+f"(c[3])
        : "r"(a[0]), "r"(a[1]), "r"(a[2]), "r"(a[3]), "r"(b[0]), "r"(b[1]));
}
__device__ __forceinline__ __half2 h2f(float x, float y) {
    return __halves2half2(__float2half_rn(x), __float2half_rn(y));
}

// ---------------- routing: 128-aligned expert groups ----------------
__global__ void routing_kernel(const int* __restrict__ sel, const int* __restrict__ adp) {
    __shared__ int s_cnt[NE], s_cur[NE];
    int tid = threadIdx.x;
    for (int p = tid; p < PTE; p += 1024) { g_tok[p] = 0; g_adp[p] = 0; }
    if (tid < NE) s_cnt[tid] = 0;
    __syncthreads();
    for (int i = tid; i < TE; i += blockDim.x) atomicAdd(&s_cnt[sel[i]], 1);
    __syncthreads();
    if (tid == 0) {
        int acc = 0, idx = 0;
        for (int e = 0; e < NE; e++) {
            int c = s_cnt[e];
            g_cnt[e] = c; g_off[e] = acc; s_cur[e] = acc;
            int tl = (c + 127) >> 7;
            for (int i = 0; i < tl; i++) { g_te[idx] = e; g_tm[idx] = i; idx++; }
            acc += tl << 7;             // 128-aligned
        }
        g_nt = idx;
    }
    __syncthreads();
    for (int i = tid; i < TE; i += blockDim.x) {
        int e = sel[i];
        int pos = atomicAdd(&s_cur[e], 1);
        int t = i >> 3;
        g_tok[pos] = t; g_adp[pos] = adp[t]; g_pos[i] = pos;
    }
}

// ---------------- X pre-pass: gather + half + fragment units ----------------
__global__ void xconv(const float* __restrict__ hidden) {
    int P = blockIdx.x;
    if (P >= g_nt * 8) return;
    __shared__ int tk[16];
    int tid = threadIdx.x;
    if (tid < 16) tk[tid] = g_tok[P * 16 + tid];
    __syncthreads();
    #pragma unroll
    for (int i = 0; i < 16; i++) {
        int id = tid + (i << 8);               // 4096 units: kg 0..127, lane 0..31
        int kg = id >> 5, lane = id & 31;
        int r0 = lane >> 2;
        int kl = (kg << 4) + ((lane & 3) << 1);
        const float* s0 = hidden + (size_t)tk[r0] * HD;
        const float* s1 = hidden + (size_t)tk[r0 + 8] * HD;
        float2 a0 = *(const float2*)(s0 + kl);
        float2 a1 = *(const float2*)(s1 + kl);
        float2 b0 = *(const float2*)(s0 + kl + 8);
        float2 b1 = *(const float2*)(s1 + kl + 8);
        __half2 o[4] = { h2f(a0.x, a0.y), h2f(a1.x, a1.y), h2f(b0.x, b0.y), h2f(b1.x, b1.y) };
        *(uint4*)(g_Xg + (((size_t)P * KGX + kg) * 32 + lane) * 8) = *(uint4*)o;
    }
}

// ---------------- fused gate|up weight pre-pass ----------------
// dest unit (e, ng, kg, lane): halfs[0..3]=gate col gc (k,k+1,k+8,k+9), [4..7]=up col gc
__global__ void wconv_gu(const float* __restrict__ Wg, const float* __restrict__ Wu,
                         const float* __restrict__ Bg, const float* __restrict__ Bu)
{
    __shared__ float sg[32][68], su[32][68];
    int e = blockIdx.z, ky = blockIdx.y, x = blockIdx.x;   // x: 64 real cols
    int tid = threadIdx.x;
    int rc0 = x << 6;
    #pragma unroll
    for (int i = 0; i < 2; i++) {
        int u = tid + (i << 8);              // 512 loads per matrix
        int kk = u >> 4, c4 = (u & 15) << 2;
        float4 vg = make_float4(0,0,0,0), vu = vg;
        if (ky < 64) {
            vg = *(const float4*)(Wg + ((size_t)e * HD + (ky << 5) + kk) * ID + rc0 + c4);
            vu = *(const float4*)(Wu + ((size_t)e * HD + (ky << 5) + kk) * ID + rc0 + c4);
        } else if (ky == 64) {
            vg = *(const float4*)(Bg + (((size_t)(kk >> 4) * NE + e) * 16 + (kk & 15)) * ID + rc0 + c4);
        } else {
            vu = *(const float4*)(Bu + (((size_t)(kk >> 4) * NE + e) * 16 + (kk & 15)) * ID + rc0 + c4);
        }
        sg[kk][c4]=vg.x; sg[kk][c4+1]=vg.y; sg[kk][c4+2]=vg.z; sg[kk][c4+3]=vg.w;
        su[kk][c4]=vu.x; su[kk][c4+1]=vu.y; su[kk][c4+2]=vu.z; su[kk][c4+3]=vu.w;
    }
    __syncthreads();
    #pragma unroll
    for (int i = 0; i < 2; i++) {
        int u = tid + (i << 8);              // 512 units
        int ngl = u >> 6, kg = (u >> 5) & 1, lane = u & 31;
        int gc = (ngl << 3) + (lane >> 2);   // local col 0..63
        int kl = (kg << 4) + ((lane & 3) << 1);
        __half h[8];
        h[0]=__float2half_rn(sg[kl][gc]);   h[1]=__float2half_rn(sg[kl+1][gc]);
        h[2]=__float2half_rn(sg[kl+8][gc]); h[3]=__float2half_rn(sg[kl+9][gc]);
        h[4]=__float2half_rn(su[kl][gc]);   h[5]=__float2half_rn(su[kl+1][gc]);
        h[6]=__float2half_rn(su[kl+8][gc]); h[7]=__float2half_rn(su[kl+9][gc]);
        *(uint4*)(g_Wgu + ((((size_t)e*128 + (x<<3) + ngl) * KGX + (ky<<1) + kg) * 32 + lane) * 8) = *(uint4*)h;
    }
}

// ---------------- down weight pre-pass ----------------
__global__ void wconv_d(const float* __restrict__ Wd, const float* __restrict__ Bd) {
    __shared__ float s[32][132];
    int e = blockIdx.z, ky = blockIdx.y, x = blockIdx.x;
    int tid = threadIdx.x;
    int n0 = x << 7;
    #pragma unroll
    for (int i = 0; i < 4; i++) {
        int u = tid + (i << 8);
        int kk = u >> 5, c4 = (u & 31) << 2;
        float4 v;
        if (ky < 32) v = *(const float4*)(Wd + ((size_t)e * ID + (ky << 5) + kk) * HD + n0 + c4);
        else         v = *(const float4*)(Bd + (((size_t)(kk >> 4) * NE + e) * 16 + (kk & 15)) * HD + n0 + c4);
        s[kk][c4]=v.x; s[kk][c4+1]=v.y; s[kk][c4+2]=v.z; s[kk][c4+3]=v.w;
    }
    __syncthreads();
    #pragma unroll
    for (int i = 0; i < 2; i++) {
        int u = tid + (i << 8);
        int ngl = u >> 6, kg = (u >> 5) & 1, lane = u & 31;
        int c = (ngl << 4) + (lane >> 2);
        int kl = (kg << 4) + ((lane & 3) << 1);
        __half h[8];
        h[0]=__float2half_rn(s[kl][c]);     h[1]=__float2half_rn(s[kl+1][c]);
        h[2]=__float2half_rn(s[kl+8][c]);   h[3]=__float2half_rn(s[kl+9][c]);
        h[4]=__float2half_rn(s[kl][c+8]);   h[5]=__float2half_rn(s[kl+1][c+8]);
        h[6]=__float2half_rn(s[kl+8][c+8]); h[7]=__float2half_rn(s[kl+9][c+8]);
        *(uint4*)(g_Wd + ((((size_t)e*128 + (x<<3) + ngl) * KGH + (ky<<1) + kg) * 32 + lane) * 8) = *(uint4*)h;
    }
}

// ---------------- loraA pre-pass (fragment units) ----------------
__global__ void aconv(const float* __restrict__ Ag, const float* __restrict__ Au,
                      const float* __restrict__ Ad)
{
    int e = blockIdx.x, which = blockIdx.y, tid = threadIdx.x;
    int K = (which == 2) ? ID : HD;
    int KG = K >> 4;
    const float* A = (which == 0) ? Ag : (which == 1) ? Au : Ad;
    int units = 2 * KG * 32;
    for (int u = tid; u < units; u += 256) {
        int ngl = u / (KG * 32);
        int rem = u - ngl * KG * 32;
        int kg = rem >> 5, lane = rem & 31;
        int n0 = lane >> 2;
        int k = (kg << 4) + ((lane & 3) << 1);
        int a = ngl;                       // adapter = local ngroup
        const float* b0 = A + (((size_t)a * NE + e) * K + k) * 16;
        __half h[8];
        h[0]=__float2half_rn(b0[n0]);            h[1]=__float2half_rn(b0[16 + n0]);
        h[2]=__float2half_rn(b0[8*16 + n0]);     h[3]=__float2half_rn(b0[9*16 + n0]);
        h[4]=__float2half_rn(b0[n0+8]);          h[5]=__float2half_rn(b0[16 + n0+8]);
        h[6]=__float2half_rn(b0[8*16 + n0+8]);   h[7]=__float2half_rn(b0[9*16 + n0+8]);
        __half* dst = (which == 2)
            ? g_Adt + ((((size_t)e*2 + ngl) * 64 + kg) * 32 + lane) * 8
            : g_Azt + ((((size_t)e*4 + (which << 1) + ngl) * 128 + kg) * 32 + lane) * 8;
        *(uint4*)dst = *(uint4*)h;
    }
}

// ---------------- unified fp16 grouped GEMM, fragment units ----------------
// EPI 0: fp32 natural store (down)  1: fused gate|up -> h units in Gh
// EPI 2: masked Zgu -> Xg kgrps 128+  3: masked Zd -> Gh kgrps 64+
template<int N_, int EPI>
__global__ __launch_bounds__(256, 2)
void mm(const __half* __restrict__ X, int KGXp,
        const __half* __restrict__ Wt, int KGW, int NGT, int KT,
        void* __restrict__ OutV)
{
    if ((int)blockIdx.y >= g_nt) return;
    const int e   = g_te[blockIdx.y];
    const int m0  = g_tm[blockIdx.y] << 7;
    const int posbase = g_off[e] + m0;
    const int Pbase = posbase >> 4;
    const int n0  = blockIdx.x * N_;
    const int tid = threadIdx.x, lane = tid & 31, wid = tid >> 5;
    constexpr int MW = 256 / N_;
    constexpr int MF = 8 / MW;
    constexpr int XSB = 8192;                 // X stage bytes
    constexpr int WSB = N_ * 64;              // B stage bytes
    constexpr int STGB = XSB + WSB;
    const int rg0 = (wid % MW) * MF;          // row-group base (16-row units)
    const int cb4 = (wid / MW) * 2;           // ngroup base within warp cols (2 ngroups)

    extern __shared__ __half sm[];
    const uint32_t smb = smem_u32(sm);
    const size_t WB = (size_t)e * NGT + (n0 >> 4);

    auto issue = [&](int kc, int buf) {
        #pragma unroll
        for (int i = 0; i < 2; i++) {
            int u = tid + (i << 8);
            cpa16(smb + buf * STGB + u * 16,
                  X + (((size_t)(Pbase + (u >> 6)) * KGXp + (kc << 1) + ((u >> 5) & 1)) * 32 + (u & 31)) * 8);
        }
        #pragma unroll
        for (int i = 0; i < (N_ >= 128 ? 2 : 1); i++) {
            int v = tid + (i << 8);
            if (N_ >= 64 || v < (N_ << 2))
                cpa16(smb + buf * STGB + XSB + v * 16,
                      Wt + (((WB + (v >> 6)) * KGW + (kc << 1) + ((v >> 5) & 1)) * 32 + (v & 31)) * 8);
        }
    };

    float acc[MF][4][4];
    #pragma unroll
    for (int i = 0; i < MF; i++)
        #pragma unroll
        for (int j = 0; j < 4; j++) { acc[i][j][0]=0.f; acc[i][j][1]=0.f; acc[i][j][2]=0.f; acc[i][j][3]=0.f; }

    issue(0, 0); cpa_commit();
    issue(1, 1); cpa_commit();

    for (int kc = 0; kc < KT; kc++) {
        cpa_wait1();
        __syncthreads();
        if (kc + 2 < KT) issue(kc + 2, (kc + 2) % 3);
        cpa_commit();
        const __half* xs = sm + (kc % 3) * (STGB / 2);
        const __half* ws = xs + XSB / 2;
        #pragma unroll
        for (int ks = 0; ks < 2; ks++) {
            uint32_t A[MF][4];
            #pragma unroll
            for (int mf = 0; mf < MF; mf++) {
                uint4 q = *(const uint4*)(xs + ((((rg0 + mf) << 1) + ks) * 32 + lane) * 8);
                A[mf][0] = q.x; A[mf][1] = q.y; A[mf][2] = q.z; A[mf][3] = q.w;
            }
            uint32_t B[4][2];
            #pragma unroll
            for (int pi = 0; pi < 2; pi++) {
                uint4 q = *(const uint4*)(ws + ((((cb4 + pi) << 1) + ks) * 32 + lane) * 8);
                B[2*pi][0] = q.x; B[2*pi][1] = q.y;
                B[2*pi+1][0] = q.z; B[2*pi+1][1] = q.w;
            }
            #pragma unroll
            for (int mf = 0; mf < MF; mf++)
                #pragma unroll
                for (int nf = 0; nf < 4; nf++)
                    mma16(acc[mf][nf], A[mf], B[nf]);
        }
    }

    // ---------------- epilogue ----------------
    const int outlane = ((lane >> 2) << 2) + (lane & 3);
    #pragma unroll
    for (int mf = 0; mf < MF; mf++) {
        int rl0 = ((rg0 + mf) << 4) + (lane >> 2);
        int p0 = posbase + rl0;
        if (EPI == 0) {
            float* Out = (float*)OutV;
            #pragma unroll
            for (int nf = 0; nf < 4; nf++) {
                int cl = (cb4 << 4) + (nf << 3) + ((lane & 3) << 1);
                *(float2*)(Out + (size_t)p0 * HD + n0 + cl) = make_float2(acc[mf][nf][0], acc[mf][nf][1]);
                *(float2*)(Out + (size_t)(p0 + 8) * HD + n0 + cl) = make_float2(acc[mf][nf][2], acc[mf][nf][3]);
            }
        } else if (EPI == 1) {
            __half* Out = (__half*)OutV;
            int kq = ((n0 >> 1) + (cb4 << 3)) >> 4;
            float h[8];
            #pragma unroll
            for (int pi = 0; pi < 2; pi++) {
                #pragma unroll
                for (int q = 0; q < 4; q++) {
                    float g = acc[mf][2*pi][q], u = acc[mf][2*pi+1][q];
                    h[pi*4 + q] = u * g / (1.f + expf(-g));
                }
            }
            __half2 o[4] = { h2f(h[0],h[1]), h2f(h[2],h[3]), h2f(h[4],h[5]), h2f(h[6],h[7]) };
            size_t P = (size_t)(Pbase + rg0 + mf);
            *(uint4*)(Out + ((P * KGH + kq) * 32 + outlane) * 8) = *(uint4*)o;
        } else {
            __half* Out = (__half*)OutV;
            int a0 = g_adp[p0], a1 = g_adp[p0 + 8];
            size_t P = (size_t)(Pbase + rg0 + mf);
            #pragma unroll
            for (int P2 = 0; P2 < 2; P2++) {
                int slot = (cb4 + P2) & 1;          // adapter of ngroup cb4+P2 (FIX: was ((cb4>>1)+P2)&1)
                int kq = (EPI == 2 ? 128 : 64) + cb4 + P2;
                float v0 = (slot == a0) ? 1.f : 0.f;
                float v1 = (slot == a1) ? 1.f : 0.f;
                __half2 o[4] = {
                    h2f(acc[mf][2*P2][0]*v0,   acc[mf][2*P2][1]*v0),
                    h2f(acc[mf][2*P2][2]*v1,   acc[mf][2*P2][3]*v1),
                    h2f(acc[mf][2*P2+1][0]*v0, acc[mf][2*P2+1][1]*v0),
                    h2f(acc[mf][2*P2+1][2]*v1, acc[mf][2*P2+1][3]*v1) };
                int KGO = (EPI == 2) ? KGX : KGH;
                *(uint4*)(Out + ((P * KGO + kq) * 32 + outlane) * 8) = *(uint4*)o;
            }
        }
    }
}

// ---------------- combine ----------------
__global__ void combine_kernel(const float* __restrict__ rw, float* __restrict__ out) {
    int t = blockIdx.x;
    __shared__ int s_pos[TOPK];
    __shared__ float s_w[TOPK];
    if (threadIdx.x < TOPK) {
        s_pos[threadIdx.x] = g_pos[t*TOPK + threadIdx.x];
        s_w[threadIdx.x]   = rw[t*TOPK + threadIdx.x];
    }
    __syncthreads();
    for (int h = threadIdx.x * 4; h < HD; h += blockDim.x * 4) {
        float4 acc = make_float4(0.f, 0.f, 0.f, 0.f);
        #pragma unroll
        for (int k = 0; k < TOPK; k++) {
            const float4 v = *(const float4*)(g_O + (size_t)s_pos[k]*HD + h);
            float w = s_w[k];
            acc.x += w*v.x; acc.y += w*v.y; acc.z += w*v.z; acc.w += w*v.w;
        }
        *(float4*)(out + (size_t)t*HD + h) = acc;
    }
}

#define SM128 (3*(8192 + 128*64))
#define SM64  (3*(8192 +  64*64))
#define SM32  (3*(8192 +  32*64))

extern "C" void kernel_launch(void* const* d_in, const int* in_sizes, int n_in,
                              void* d_out, int out_size) {
    const float* hidden = (const float*)d_in[0];
    const int*   sel    = (const int*)  d_in[1];
    const float* rw     = (const float*)d_in[2];
    const int*   adp    = (const int*)  d_in[3];
    const float* Wg     = (const float*)d_in[4];
    const float* Ag     = (const float*)d_in[5];
    const float* Bg     = (const float*)d_in[6];
    const float* Wu     = (const float*)d_in[7];
    const float* Au     = (const float*)d_in[8];
    const float* Bu     = (const float*)d_in[9];
    const float* Wd     = (const float*)d_in[10];
    const float* Ad     = (const float*)d_in[11];
    const float* Bd     = (const float*)d_in[12];
    float* out = (float*)d_out;

    static bool init = false;
    if (!init) {
        cudaFuncSetAttribute(mm<128,0>, cudaFuncAttributeMaxDynamicSharedMemorySize, SM128);
        cudaFuncSetAttribute(mm<128,1>, cudaFuncAttributeMaxDynamicSharedMemorySize, SM128);
        cudaFuncSetAttribute(mm<64,2>,  cudaFuncAttributeMaxDynamicSharedMemorySize, SM64);
        cudaFuncSetAttribute(mm<32,3>,  cudaFuncAttributeMaxDynamicSharedMemorySize, SM32);
        init = true;
    }

    __half *Xg, *Gh, *Wgu, *Wdp, *Azt, *Adt;
    float *O;
    cudaGetSymbolAddress((void**)&Xg,  g_Xg);
    cudaGetSymbolAddress((void**)&Gh,  g_Gh);
    cudaGetSymbolAddress((void**)&O,   g_O);
    cudaGetSymbolAddress((void**)&Wgu, g_Wgu);
    cudaGetSymbolAddress((void**)&Wdp, g_Wd);
    cudaGetSymbolAddress((void**)&Azt, g_Azt);
    cudaGetSymbolAddress((void**)&Adt, g_Adt);

    routing_kernel<<<1, 1024>>>(sel, adp);

    // pre-passes
    xconv<<<MAXT*8, 256>>>(hidden);
    wconv_gu<<<dim3(16, 66, NE), 256>>>(Wg, Wu, Bg, Bu);
    wconv_d<<<dim3(16, 33, NE), 256>>>(Wd, Bd);
    aconv<<<dim3(NE, 3), 256>>>(Ag, Au, Ad);

    // Z(gate|up) -> Xg kgrps 128..131 (adapter-masked)
    mm<64,2><<<dim3(1, MAXT), 256, SM64>>>(Xg, KGX, Azt, 128, 4, 64, Xg);
    // fused gate+up -> Gh (h = silu(g)*u)
    mm<128,1><<<dim3(16, MAXT), 256, SM128>>>(Xg, KGX, Wgu, KGX, 128, 66, Gh);
    // Z(down) -> Gh kgrps 64..65
    mm<32,3><<<dim3(1, MAXT), 256, SM32>>>(Gh, KGH, Adt, 64, 2, 32, Gh);
    // down -> O (fp32 natural)
    mm<128,0><<<dim3(16, MAXT), 256, SM128>>>(Gh, KGH, Wdp, KGH, 128, 33, O);

    combine_kernel<<<NT, 256>>>(rw, out);
}

// round 13
// speedup vs baseline: 2.8786x; 1.0774x over previous
#include <cuda_runtime.h>
#include <cuda_fp16.h>
#include <cstdint>
#include <math.h>

#define NE 32
#define TOPK 8
#define HD 2048
#define ID 1024
#define NT 4096
#define TE (NT*TOPK)
#define MAXT 288
#define PTE (MAXT*128)      // padded position space (128-aligned expert groups)

#define KGX 132             // Xg kgroups: 128 X | 2 Zg | 2 Zu   (16 k each)
#define KGH 68              // Gh kgroups: 64 h | 2 Zd | 2 zero-pad

__device__ int g_cnt[NE], g_off[NE];
__device__ int g_tok[PTE], g_adp[PTE], g_pos[TE];
__device__ int g_te[MAXT], g_tm[MAXT], g_nt;
__device__ __half g_Xg[(size_t)PTE*KGX*16];            // fragment units
__device__ __half g_Gh[(size_t)PTE*KGH*16];            // kg 66,67 stay zero (never written)
__device__ __half g_O [(size_t)PTE*HD];                // down output, fp16
__device__ __half g_Wgu[(size_t)NE*128*KGX*256];       // fused gate|up image
__device__ __half g_Wd [(size_t)NE*128*KGH*256];       // kg 66,67 stay zero
__device__ __half g_Azt[(size_t)NE*4*128*256];
__device__ __half g_Adt[(size_t)NE*2*64*256];

__device__ __forceinline__ uint32_t smem_u32(const void* p) {
    uint32_t a;
    asm("{ .reg .u64 t; cvta.to.shared.u64 t, %1; cvt.u32.u64 %0, t; }" : "=r"(a) : "l"(p));
    return a;
}
__device__ __forceinline__ void cpa16(uint32_t dst, const void* src) {
    asm volatile("cp.async.cg.shared.global [%0], [%1], 16;" :: "r"(dst), "l"(src) : "memory");
}
__device__ __forceinline__ void cpa_commit() { asm volatile("cp.async.commit_group;" ::: "memory"); }
__device__ __forceinline__ void cpa_wait1()  { asm volatile("cp.async.wait_group 1;" ::: "memory"); }
__device__ __forceinline__ void mma16(float* c, const uint32_t* a, const uint32_t* b) {
    asm volatile(
        "mma.sync.aligned.m16n8k16.row.col.f32.f16.f16.f32 "
        "{%0,%1,%2,%3}, {%4,%5,%6,%7}, {%8,%9}, {%0,%1,%2,%3};\n"
        : "+f"(c[0]), "+f"(c[1]), "+f"(c[2]), "+f"(c[3])
        : "r"(a[0]), "r"(a[1]), "r"(a[2]), "r"(a[3]), "r"(b[0]), "r"(b[1]));
}
__device__ __forceinline__ __half2 h2f(float x, float y) {
    return __halves2half2(__float2half_rn(x), __float2half_rn(y));
}

// ---------------- routing: 128-aligned expert groups ----------------
__global__ void routing_kernel(const int* __restrict__ sel, const int* __restrict__ adp) {
    __shared__ int s_cnt[NE], s_cur[NE];
    int tid = threadIdx.x;
    for (int p = tid; p < PTE; p += 1024) { g_tok[p] = 0; g_adp[p] = 0; }
    if (tid < NE) s_cnt[tid] = 0;
    __syncthreads();
    for (int i = tid; i < TE; i += blockDim.x) atomicAdd(&s_cnt[sel[i]], 1);
    __syncthreads();
    if (tid == 0) {
        int acc = 0, idx = 0;
        for (int e = 0; e < NE; e++) {
            int c = s_cnt[e];
            g_cnt[e] = c; g_off[e] = acc; s_cur[e] = acc;
            int tl = (c + 127) >> 7;
            for (int i = 0; i < tl; i++) { g_te[idx] = e; g_tm[idx] = i; idx++; }
            acc += tl << 7;             // 128-aligned
        }
        g_nt = idx;
    }
    __syncthreads();
    for (int i = tid; i < TE; i += blockDim.x) {
        int e = sel[i];
        int pos = atomicAdd(&s_cur[e], 1);
        int t = i >> 3;
        g_tok[pos] = t; g_adp[pos] = adp[t]; g_pos[i] = pos;
    }
}

// ---------------- X pre-pass: gather + half + fragment units ----------------
__global__ void xconv(const float* __restrict__ hidden) {
    int P = blockIdx.x;
    if (P >= g_nt * 8) return;
    __shared__ int tk[16];
    int tid = threadIdx.x;
    if (tid < 16) tk[tid] = g_tok[P * 16 + tid];
    __syncthreads();
    #pragma unroll
    for (int i = 0; i < 16; i++) {
        int id = tid + (i << 8);               // 4096 units: kg 0..127, lane 0..31
        int kg = id >> 5, lane = id & 31;
        int r0 = lane >> 2;
        int kl = (kg << 4) + ((lane & 3) << 1);
        const float* s0 = hidden + (size_t)tk[r0] * HD;
        const float* s1 = hidden + (size_t)tk[r0 + 8] * HD;
        float2 a0 = *(const float2*)(s0 + kl);
        float2 a1 = *(const float2*)(s1 + kl);
        float2 b0 = *(const float2*)(s0 + kl + 8);
        float2 b1 = *(const float2*)(s1 + kl + 8);
        __half2 o[4] = { h2f(a0.x, a0.y), h2f(a1.x, a1.y), h2f(b0.x, b0.y), h2f(b1.x, b1.y) };
        *(uint4*)(g_Xg + (((size_t)P * KGX + kg) * 32 + lane) * 8) = *(uint4*)o;
    }
}

// ---------------- fused gate|up weight pre-pass ----------------
__global__ void wconv_gu(const float* __restrict__ Wg, const float* __restrict__ Wu,
                         const float* __restrict__ Bg, const float* __restrict__ Bu)
{
    __shared__ float sg[32][68], su[32][68];
    int e = blockIdx.z, ky = blockIdx.y, x = blockIdx.x;   // x: 64 real cols
    int tid = threadIdx.x;
    int rc0 = x << 6;
    #pragma unroll
    for (int i = 0; i < 2; i++) {
        int u = tid + (i << 8);
        int kk = u >> 4, c4 = (u & 15) << 2;
        float4 vg = make_float4(0,0,0,0), vu = vg;
        if (ky < 64) {
            vg = *(const float4*)(Wg + ((size_t)e * HD + (ky << 5) + kk) * ID + rc0 + c4);
            vu = *(const float4*)(Wu + ((size_t)e * HD + (ky << 5) + kk) * ID + rc0 + c4);
        } else if (ky == 64) {
            vg = *(const float4*)(Bg + (((size_t)(kk >> 4) * NE + e) * 16 + (kk & 15)) * ID + rc0 + c4);
        } else {
            vu = *(const float4*)(Bu + (((size_t)(kk >> 4) * NE + e) * 16 + (kk & 15)) * ID + rc0 + c4);
        }
        sg[kk][c4]=vg.x; sg[kk][c4+1]=vg.y; sg[kk][c4+2]=vg.z; sg[kk][c4+3]=vg.w;
        su[kk][c4]=vu.x; su[kk][c4+1]=vu.y; su[kk][c4+2]=vu.z; su[kk][c4+3]=vu.w;
    }
    __syncthreads();
    #pragma unroll
    for (int i = 0; i < 2; i++) {
        int u = tid + (i << 8);
        int ngl = u >> 6, kg = (u >> 5) & 1, lane = u & 31;
        int gc = (ngl << 3) + (lane >> 2);
        int kl = (kg << 4) + ((lane & 3) << 1);
        __half h[8];
        h[0]=__float2half_rn(sg[kl][gc]);   h[1]=__float2half_rn(sg[kl+1][gc]);
        h[2]=__float2half_rn(sg[kl+8][gc]); h[3]=__float2half_rn(sg[kl+9][gc]);
        h[4]=__float2half_rn(su[kl][gc]);   h[5]=__float2half_rn(su[kl+1][gc]);
        h[6]=__float2half_rn(su[kl+8][gc]); h[7]=__float2half_rn(su[kl+9][gc]);
        *(uint4*)(g_Wgu + ((((size_t)e*128 + (x<<3) + ngl) * KGX + (ky<<1) + kg) * 32 + lane) * 8) = *(uint4*)h;
    }
}

// ---------------- down weight pre-pass ----------------
__global__ void wconv_d(const float* __restrict__ Wd, const float* __restrict__ Bd) {
    __shared__ float s[32][132];
    int e = blockIdx.z, ky = blockIdx.y, x = blockIdx.x;
    int tid = threadIdx.x;
    int n0 = x << 7;
    #pragma unroll
    for (int i = 0; i < 4; i++) {
        int u = tid + (i << 8);
        int kk = u >> 5, c4 = (u & 31) << 2;
        float4 v;
        if (ky < 32) v = *(const float4*)(Wd + ((size_t)e * ID + (ky << 5) + kk) * HD + n0 + c4);
        else         v = *(const float4*)(Bd + (((size_t)(kk >> 4) * NE + e) * 16 + (kk & 15)) * HD + n0 + c4);
        s[kk][c4]=v.x; s[kk][c4+1]=v.y; s[kk][c4+2]=v.z; s[kk][c4+3]=v.w;
    }
    __syncthreads();
    #pragma unroll
    for (int i = 0; i < 2; i++) {
        int u = tid + (i << 8);
        int ngl = u >> 6, kg = (u >> 5) & 1, lane = u & 31;
        int c = (ngl << 4) + (lane >> 2);
        int kl = (kg << 4) + ((lane & 3) << 1);
        __half h[8];
        h[0]=__float2half_rn(s[kl][c]);     h[1]=__float2half_rn(s[kl+1][c]);
        h[2]=__float2half_rn(s[kl+8][c]);   h[3]=__float2half_rn(s[kl+9][c]);
        h[4]=__float2half_rn(s[kl][c+8]);   h[5]=__float2half_rn(s[kl+1][c+8]);
        h[6]=__float2half_rn(s[kl+8][c+8]); h[7]=__float2half_rn(s[kl+9][c+8]);
        *(uint4*)(g_Wd + ((((size_t)e*128 + (x<<3) + ngl) * KGH + (ky<<1) + kg) * 32 + lane) * 8) = *(uint4*)h;
    }
}

// ---------------- loraA pre-pass (fragment units) ----------------
__global__ void aconv(const float* __restrict__ Ag, const float* __restrict__ Au,
                      const float* __restrict__ Ad)
{
    int e = blockIdx.x, which = blockIdx.y, tid = threadIdx.x;
    int K = (which == 2) ? ID : HD;
    int KG = K >> 4;
    const float* A = (which == 0) ? Ag : (which == 1) ? Au : Ad;
    int units = 2 * KG * 32;
    for (int u = tid; u < units; u += 256) {
        int ngl = u / (KG * 32);
        int rem = u - ngl * KG * 32;
        int kg = rem >> 5, lane = rem & 31;
        int n0 = lane >> 2;
        int k = (kg << 4) + ((lane & 3) << 1);
        int a = ngl;
        const float* b0 = A + (((size_t)a * NE + e) * K + k) * 16;
        __half h[8];
        h[0]=__float2half_rn(b0[n0]);            h[1]=__float2half_rn(b0[16 + n0]);
        h[2]=__float2half_rn(b0[8*16 + n0]);     h[3]=__float2half_rn(b0[9*16 + n0]);
        h[4]=__float2half_rn(b0[n0+8]);          h[5]=__float2half_rn(b0[16 + n0+8]);
        h[6]=__float2half_rn(b0[8*16 + n0+8]);   h[7]=__float2half_rn(b0[9*16 + n0+8]);
        __half* dst = (which == 2)
            ? g_Adt + ((((size_t)e*2 + ngl) * 64 + kg) * 32 + lane) * 8
            : g_Azt + ((((size_t)e*4 + (which << 1) + ngl) * 128 + kg) * 32 + lane) * 8;
        *(uint4*)dst = *(uint4*)h;
    }
}

// ---------------- unified fp16 grouped GEMM, 64-k double chunks ----------------
// EPI 0: half natural store (down)  1: fused gate|up -> h units in Gh
// EPI 2: masked Zgu -> Xg kgrps 128+  3: masked Zd -> Gh kgrps 64+
template<int N_, int EPI>
__global__ __launch_bounds__(256, 2)
void mm(const __half* __restrict__ X, int KGXp,
        const __half* __restrict__ Wt, int KGW, int NGT, int KT,
        void* __restrict__ OutV)
{
    if ((int)blockIdx.y >= g_nt) return;
    const int e   = g_te[blockIdx.y];
    const int m0  = g_tm[blockIdx.y] << 7;
    const int posbase = g_off[e] + m0;
    const int Pbase = posbase >> 4;
    const int n0  = blockIdx.x * N_;
    const int tid = threadIdx.x, lane = tid & 31, wid = tid >> 5;
    constexpr int MW = 256 / N_;
    constexpr int MF = 8 / MW;
    constexpr int XSB = 16384;                // X stage bytes (128 rows x 64 k)
    constexpr int WSB = N_ * 128;             // B stage bytes
    constexpr int STGB = XSB + WSB;
    const int rg0 = (wid % MW) * MF;          // row-group base (16-row units)
    const int cb4 = (wid / MW) * 2;           // ngroup base (2 ngroups per warp)

    extern __shared__ __half sm[];
    const uint32_t smb = smem_u32(sm);
    const size_t WB = (size_t)e * NGT + (n0 >> 4);

    auto issue = [&](int kc, int buf) {
        #pragma unroll
        for (int i = 0; i < 4; i++) {
            int u = tid + (i << 8);
            cpa16(smb + buf * STGB + u * 16,
                  X + (((size_t)(Pbase + (u >> 7)) * KGXp + (kc << 2) + ((u >> 5) & 3)) * 32 + (u & 31)) * 8);
        }
        #pragma unroll
        for (int i = 0; i < (N_ >> 5); i++) {
            int v = tid + (i << 8);
            cpa16(smb + buf * STGB + XSB + v * 16,
                  Wt + (((WB + (v >> 7)) * KGW + (kc << 2) + ((v >> 5) & 3)) * 32 + (v & 31)) * 8);
        }
    };

    float acc[MF][4][4];
    #pragma unroll
    for (int i = 0; i < MF; i++)
        #pragma unroll
        for (int j = 0; j < 4; j++) { acc[i][j][0]=0.f; acc[i][j][1]=0.f; acc[i][j][2]=0.f; acc[i][j][3]=0.f; }

    issue(0, 0); cpa_commit();
    issue(1, 1); cpa_commit();

    for (int kc = 0; kc < KT; kc++) {
        cpa_wait1();
        __syncthreads();
        if (kc + 2 < KT) issue(kc + 2, (kc + 2) % 3);
        cpa_commit();
        const __half* xs = sm + (kc % 3) * (STGB / 2);
        const __half* ws = xs + XSB / 2;
        #pragma unroll
        for (int ks = 0; ks < 4; ks++) {
            uint32_t A[MF][4];
            #pragma unroll
            for (int mf = 0; mf < MF; mf++) {
                uint4 q = *(const uint4*)(xs + ((((rg0 + mf) << 2) + ks) * 32 + lane) * 8);
                A[mf][0] = q.x; A[mf][1] = q.y; A[mf][2] = q.z; A[mf][3] = q.w;
            }
            uint32_t B[4][2];
            #pragma unroll
            for (int pi = 0; pi < 2; pi++) {
                uint4 q = *(const uint4*)(ws + ((((cb4 + pi) << 2) + ks) * 32 + lane) * 8);
                B[2*pi][0] = q.x; B[2*pi][1] = q.y;
                B[2*pi+1][0] = q.z; B[2*pi+1][1] = q.w;
            }
            #pragma unroll
            for (int mf = 0; mf < MF; mf++)
                #pragma unroll
                for (int nf = 0; nf < 4; nf++)
                    mma16(acc[mf][nf], A[mf], B[nf]);
        }
    }

    // ---------------- epilogue ----------------
    const int outlane = ((lane >> 2) << 2) + (lane & 3);
    #pragma unroll
    for (int mf = 0; mf < MF; mf++) {
        int rl0 = ((rg0 + mf) << 4) + (lane >> 2);
        int p0 = posbase + rl0;
        if (EPI == 0) {
            __half* Out = (__half*)OutV;
            #pragma unroll
            for (int nf = 0; nf < 4; nf++) {
                int cl = (cb4 << 4) + (nf << 3) + ((lane & 3) << 1);
                *(__half2*)(Out + (size_t)p0 * HD + n0 + cl) = h2f(acc[mf][nf][0], acc[mf][nf][1]);
                *(__half2*)(Out + (size_t)(p0 + 8) * HD + n0 + cl) = h2f(acc[mf][nf][2], acc[mf][nf][3]);
            }
        } else if (EPI == 1) {
            __half* Out = (__half*)OutV;
            int kq = ((n0 >> 1) + (cb4 << 3)) >> 4;
            float h[8];
            #pragma unroll
            for (int pi = 0; pi < 2; pi++) {
                #pragma unroll
                for (int q = 0; q < 4; q++) {
                    float g = acc[mf][2*pi][q], u = acc[mf][2*pi+1][q];
                    h[pi*4 + q] = u * g / (1.f + expf(-g));
                }
            }
            __half2 o[4] = { h2f(h[0],h[1]), h2f(h[2],h[3]), h2f(h[4],h[5]), h2f(h[6],h[7]) };
            size_t P = (size_t)(Pbase + rg0 + mf);
            *(uint4*)(Out + ((P * KGH + kq) * 32 + outlane) * 8) = *(uint4*)o;
        } else {
            __half* Out = (__half*)OutV;
            int a0 = g_adp[p0], a1 = g_adp[p0 + 8];
            size_t P = (size_t)(Pbase + rg0 + mf);
            #pragma unroll
            for (int P2 = 0; P2 < 2; P2++) {
                int slot = (cb4 + P2) & 1;
                int kq = (EPI == 2 ? 128 : 64) + cb4 + P2;
                float v0 = (slot == a0) ? 1.f : 0.f;
                float v1 = (slot == a1) ? 1.f : 0.f;
                __half2 o[4] = {
                    h2f(acc[mf][2*P2][0]*v0,   acc[mf][2*P2][1]*v0),
                    h2f(acc[mf][2*P2][2]*v1,   acc[mf][2*P2][3]*v1),
                    h2f(acc[mf][2*P2+1][0]*v0, acc[mf][2*P2+1][1]*v0),
                    h2f(acc[mf][2*P2+1][2]*v1, acc[mf][2*P2+1][3]*v1) };
                int KGO = (EPI == 2) ? KGX : KGH;
                *(uint4*)(Out + ((P * KGO + kq) * 32 + outlane) * 8) = *(uint4*)o;
            }
        }
    }
}

// ---------------- combine (half O) ----------------
__global__ void combine_kernel(const float* __restrict__ rw, float* __restrict__ out) {
    int t = blockIdx.x;
    __shared__ int s_pos[TOPK];
    __shared__ float s_w[TOPK];
    if (threadIdx.x < TOPK) {
        s_pos[threadIdx.x] = g_pos[t*TOPK + threadIdx.x];
        s_w[threadIdx.x]   = rw[t*TOPK + threadIdx.x];
    }
    __syncthreads();
    int h = threadIdx.x * 8;                  // 256 threads x 8 = 2048 = HD
    float acc[8] = {0.f,0.f,0.f,0.f,0.f,0.f,0.f,0.f};
    #pragma unroll
    for (int k = 0; k < TOPK; k++) {
        const __half2* v = (const __half2*)(g_O + (size_t)s_pos[k]*HD + h);
        float w = s_w[k];
        #pragma unroll
        for (int q = 0; q < 4; q++) {
            float2 f = __half22float2(v[q]);
            acc[2*q]   += w * f.x;
            acc[2*q+1] += w * f.y;
        }
    }
    float4* o = (float4*)(out + (size_t)t*HD + h);
    o[0] = make_float4(acc[0], acc[1], acc[2], acc[3]);
    o[1] = make_float4(acc[4], acc[5], acc[6], acc[7]);
}

#define SM128 (3*(16384 + 128*128))
#define SM64  (3*(16384 +  64*128))
#define SM32  (3*(16384 +  32*128))

extern "C" void kernel_launch(void* const* d_in, const int* in_sizes, int n_in,
                              void* d_out, int out_size) {
    const float* hidden = (const float*)d_in[0];
    const int*   sel    = (const int*)  d_in[1];
    const float* rw     = (const float*)d_in[2];
    const int*   adp    = (const int*)  d_in[3];
    const float* Wg     = (const float*)d_in[4];
    const float* Ag     = (const float*)d_in[5];
    const float* Bg     = (const float*)d_in[6];
    const float* Wu     = (const float*)d_in[7];
    const float* Au     = (const float*)d_in[8];
    const float* Bu     = (const float*)d_in[9];
    const float* Wd     = (const float*)d_in[10];
    const float* Ad     = (const float*)d_in[11];
    const float* Bd     = (const float*)d_in[12];
    float* out = (float*)d_out;

    static bool init = false;
    if (!init) {
        cudaFuncSetAttribute(mm<128,0>, cudaFuncAttributeMaxDynamicSharedMemorySize, SM128);
        cudaFuncSetAttribute(mm<128,1>, cudaFuncAttributeMaxDynamicSharedMemorySize, SM128);
        cudaFuncSetAttribute(mm<64,2>,  cudaFuncAttributeMaxDynamicSharedMemorySize, SM64);
        cudaFuncSetAttribute(mm<32,3>,  cudaFuncAttributeMaxDynamicSharedMemorySize, SM32);
        init = true;
    }

    __half *Xg, *Gh, *O, *Wgu, *Wdp, *Azt, *Adt;
    cudaGetSymbolAddress((void**)&Xg,  g_Xg);
    cudaGetSymbolAddress((void**)&Gh,  g_Gh);
    cudaGetSymbolAddress((void**)&O,   g_O);
    cudaGetSymbolAddress((void**)&Wgu, g_Wgu);
    cudaGetSymbolAddress((void**)&Wdp, g_Wd);
    cudaGetSymbolAddress((void**)&Azt, g_Azt);
    cudaGetSymbolAddress((void**)&Adt, g_Adt);

    routing_kernel<<<1, 1024>>>(sel, adp);

    // pre-passes
    xconv<<<MAXT*8, 256>>>(hidden);
    wconv_gu<<<dim3(16, 66, NE), 256>>>(Wg, Wu, Bg, Bu);
    wconv_d<<<dim3(16, 33, NE), 256>>>(Wd, Bd);
    aconv<<<dim3(NE, 3), 256>>>(Ag, Au, Ad);

    // Z(gate|up) -> Xg kgrps 128..131 (adapter-masked); 32 double-chunks
    mm<64,2><<<dim3(1, MAXT), 256, SM64>>>(Xg, KGX, Azt, 128, 4, 32, Xg);
    // fused gate+up -> Gh (h = silu(g)*u); 33 double-chunks
    mm<128,1><<<dim3(16, MAXT), 256, SM128>>>(Xg, KGX, Wgu, KGX, 128, 33, Gh);
    // Z(down) -> Gh kgrps 64..65; 16 double-chunks
    mm<32,3><<<dim3(1, MAXT), 256, SM32>>>(Gh, KGH, Adt, 64, 2, 16, Gh);
    // down -> O (half natural); 17 double-chunks (kg 66,67 are zeros on both sides)
    mm<128,0><<<dim3(16, MAXT), 256, SM128>>>(Gh, KGH, Wdp, KGH, 128, 17, O);

    combine_kernel<<<NT, 256>>>(rw, out);
}

// round 14
// speedup vs baseline: 2.9783x; 1.0346x over previous
#include <cuda_runtime.h>
#include <cuda_fp16.h>
#include <cstdint>
#include <math.h>

#define NE 32
#define TOPK 8
#define HD 2048
#define ID 1024
#define NT 4096
#define TE (NT*TOPK)
#define MAXT 288
#define PTE (MAXT*128)      // padded position space (128-aligned expert groups)

#define KGX 132             // Xg kgroups: 128 X | 2 Zg | 2 Zu   (16 k each)
#define KGH 68              // Gh kgroups: 64 h | 2 Zd | 2 zero-pad

__device__ int g_cnt[NE], g_off[NE];
__device__ int g_tok[PTE], g_adp[PTE], g_pos[TE];
__device__ int g_te[MAXT], g_tm[MAXT], g_nt;
__device__ __half g_Xg[(size_t)PTE*KGX*16];            // fragment units
__device__ __half g_Gh[(size_t)PTE*KGH*16];            // kg 66,67 stay zero (never written)
__device__ __half g_O [(size_t)PTE*HD];                // down output, fp16
__device__ __half g_Wgu[(size_t)NE*128*KGX*256];       // fused gate|up image
__device__ __half g_Wd [(size_t)NE*128*KGH*256];       // kg 66,67 stay zero
__device__ __half g_Azt[(size_t)NE*4*128*256];
__device__ __half g_Adt[(size_t)NE*2*64*256];

__device__ __forceinline__ uint32_t smem_u32(const void* p) {
    uint32_t a;
    asm("{ .reg .u64 t; cvta.to.shared.u64 t, %1; cvt.u32.u64 %0, t; }" : "=r"(a) : "l"(p));
    return a;
}
__device__ __forceinline__ void cpa16(uint32_t dst, const void* src) {
    asm volatile("cp.async.cg.shared.global [%0], [%1], 16;" :: "r"(dst), "l"(src) : "memory");
}
__device__ __forceinline__ void cpa_commit() { asm volatile("cp.async.commit_group;" ::: "memory"); }
__device__ __forceinline__ void cpa_wait1()  { asm volatile("cp.async.wait_group 1;" ::: "memory"); }
__device__ __forceinline__ void mma16(float* c, const uint32_t* a, const uint32_t* b) {
    asm volatile(
        "mma.sync.aligned.m16n8k16.row.col.f32.f16.f16.f32 "
        "{%0,%1,%2,%3}, {%4,%5,%6,%7}, {%8,%9}, {%0,%1,%2,%3};\n"
        : "+f"(c[0]), "+f"(c[1]), "+f"(c[2]), "+f"(c[3])
        : "r"(a[0]), "r"(a[1]), "r"(a[2]), "r"(a[3]), "r"(b[0]), "r"(b[1]));
}
__device__ __forceinline__ __half2 h2f(float x, float y) {
    return __halves2half2(__float2half_rn(x), __float2half_rn(y));
}

// ---------------- routing: 128-aligned expert groups ----------------
__global__ void routing_kernel(const int* __restrict__ sel, const int* __restrict__ adp) {
    __shared__ int s_cnt[NE], s_cur[NE];
    int tid = threadIdx.x;
    for (int p = tid; p < PTE; p += 1024) { g_tok[p] = 0; g_adp[p] = 0; }
    if (tid < NE) s_cnt[tid] = 0;
    __syncthreads();
    for (int i = tid; i < TE; i += blockDim.x) atomicAdd(&s_cnt[sel[i]], 1);
    __syncthreads();
    if (tid == 0) {
        int acc = 0, idx = 0;
        for (int e = 0; e < NE; e++) {
            int c = s_cnt[e];
            g_cnt[e] = c; g_off[e] = acc; s_cur[e] = acc;
            int tl = (c + 127) >> 7;
            for (int i = 0; i < tl; i++) { g_te[idx] = e; g_tm[idx] = i; idx++; }
            acc += tl << 7;             // 128-aligned
        }
        g_nt = idx;
    }
    __syncthreads();
    for (int i = tid; i < TE; i += blockDim.x) {
        int e = sel[i];
        int pos = atomicAdd(&s_cur[e], 1);
        int t = i >> 3;
        g_tok[pos] = t; g_adp[pos] = adp[t]; g_pos[i] = pos;
    }
}

// ---------------- X pre-pass: gather + half + fragment units ----------------
__global__ void xconv(const float* __restrict__ hidden) {
    int P = blockIdx.x;
    if (P >= g_nt * 8) return;
    __shared__ int tk[16];
    int tid = threadIdx.x;
    if (tid < 16) tk[tid] = g_tok[P * 16 + tid];
    __syncthreads();
    #pragma unroll
    for (int i = 0; i < 16; i++) {
        int id = tid + (i << 8);               // 4096 units: kg 0..127, lane 0..31
        int kg = id >> 5, lane = id & 31;
        int r0 = lane >> 2;
        int kl = (kg << 4) + ((lane & 3) << 1);
        const float* s0 = hidden + (size_t)tk[r0] * HD;
        const float* s1 = hidden + (size_t)tk[r0 + 8] * HD;
        float2 a0 = *(const float2*)(s0 + kl);
        float2 a1 = *(const float2*)(s1 + kl);
        float2 b0 = *(const float2*)(s0 + kl + 8);
        float2 b1 = *(const float2*)(s1 + kl + 8);
        __half2 o[4] = { h2f(a0.x, a0.y), h2f(a1.x, a1.y), h2f(b0.x, b0.y), h2f(b1.x, b1.y) };
        *(uint4*)(g_Xg + (((size_t)P * KGX + kg) * 32 + lane) * 8) = *(uint4*)o;
    }
}

// ---------------- fused gate|up weight pre-pass ----------------
__global__ void wconv_gu(const float* __restrict__ Wg, const float* __restrict__ Wu,
                         const float* __restrict__ Bg, const float* __restrict__ Bu)
{
    __shared__ float sg[32][68], su[32][68];
    int e = blockIdx.z, ky = blockIdx.y, x = blockIdx.x;   // x: 64 real cols
    int tid = threadIdx.x;
    int rc0 = x << 6;
    #pragma unroll
    for (int i = 0; i < 2; i++) {
        int u = tid + (i << 8);
        int kk = u >> 4, c4 = (u & 15) << 2;
        float4 vg = make_float4(0,0,0,0), vu = vg;
        if (ky < 64) {
            vg = *(const float4*)(Wg + ((size_t)e * HD + (ky << 5) + kk) * ID + rc0 + c4);
            vu = *(const float4*)(Wu + ((size_t)e * HD + (ky << 5) + kk) * ID + rc0 + c4);
        } else if (ky == 64) {
            vg = *(const float4*)(Bg + (((size_t)(kk >> 4) * NE + e) * 16 + (kk & 15)) * ID + rc0 + c4);
        } else {
            vu = *(const float4*)(Bu + (((size_t)(kk >> 4) * NE + e) * 16 + (kk & 15)) * ID + rc0 + c4);
        }
        sg[kk][c4]=vg.x; sg[kk][c4+1]=vg.y; sg[kk][c4+2]=vg.z; sg[kk][c4+3]=vg.w;
        su[kk][c4]=vu.x; su[kk][c4+1]=vu.y; su[kk][c4+2]=vu.z; su[kk][c4+3]=vu.w;
    }
    __syncthreads();
    #pragma unroll
    for (int i = 0; i < 2; i++) {
        int u = tid + (i << 8);
        int ngl = u >> 6, kg = (u >> 5) & 1, lane = u & 31;
        int gc = (ngl << 3) + (lane >> 2);
        int kl = (kg << 4) + ((lane & 3) << 1);
        __half h[8];
        h[0]=__float2half_rn(sg[kl][gc]);   h[1]=__float2half_rn(sg[kl+1][gc]);
        h[2]=__float2half_rn(sg[kl+8][gc]); h[3]=__float2half_rn(sg[kl+9][gc]);
        h[4]=__float2half_rn(su[kl][gc]);   h[5]=__float2half_rn(su[kl+1][gc]);
        h[6]=__float2half_rn(su[kl+8][gc]); h[7]=__float2half_rn(su[kl+9][gc]);
        *(uint4*)(g_Wgu + ((((size_t)e*128 + (x<<3) + ngl) * KGX + (ky<<1) + kg) * 32 + lane) * 8) = *(uint4*)h;
    }
}

// ---------------- down weight pre-pass ----------------
__global__ void wconv_d(const float* __restrict__ Wd, const float* __restrict__ Bd) {
    __shared__ float s[32][132];
    int e = blockIdx.z, ky = blockIdx.y, x = blockIdx.x;
    int tid = threadIdx.x;
    int n0 = x << 7;
    #pragma unroll
    for (int i = 0; i < 4; i++) {
        int u = tid + (i << 8);
        int kk = u >> 5, c4 = (u & 31) << 2;
        float4 v;
        if (ky < 32) v = *(const float4*)(Wd + ((size_t)e * ID + (ky << 5) + kk) * HD + n0 + c4);
        else         v = *(const float4*)(Bd + (((size_t)(kk >> 4) * NE + e) * 16 + (kk & 15)) * HD + n0 + c4);
        s[kk][c4]=v.x; s[kk][c4+1]=v.y; s[kk][c4+2]=v.z; s[kk][c4+3]=v.w;
    }
    __syncthreads();
    #pragma unroll
    for (int i = 0; i < 2; i++) {
        int u = tid + (i << 8);
        int ngl = u >> 6, kg = (u >> 5) & 1, lane = u & 31;
        int c = (ngl << 4) + (lane >> 2);
        int kl = (kg << 4) + ((lane & 3) << 1);
        __half h[8];
        h[0]=__float2half_rn(s[kl][c]);     h[1]=__float2half_rn(s[kl+1][c]);
        h[2]=__float2half_rn(s[kl+8][c]);   h[3]=__float2half_rn(s[kl+9][c]);
        h[4]=__float2half_rn(s[kl][c+8]);   h[5]=__float2half_rn(s[kl+1][c+8]);
        h[6]=__float2half_rn(s[kl+8][c+8]); h[7]=__float2half_rn(s[kl+9][c+8]);
        *(uint4*)(g_Wd + ((((size_t)e*128 + (x<<3) + ngl) * KGH + (ky<<1) + kg) * 32 + lane) * 8) = *(uint4*)h;
    }
}

// ---------------- loraA pre-pass (fragment units) ----------------
__global__ void aconv(const float* __restrict__ Ag, const float* __restrict__ Au,
                      const float* __restrict__ Ad)
{
    int e = blockIdx.x, which = blockIdx.y, tid = threadIdx.x;
    int K = (which == 2) ? ID : HD;
    int KG = K >> 4;
    const float* A = (which == 0) ? Ag : (which == 1) ? Au : Ad;
    int units = 2 * KG * 32;
    for (int u = tid; u < units; u += 256) {
        int ngl = u / (KG * 32);
        int rem = u - ngl * KG * 32;
        int kg = rem >> 5, lane = rem & 31;
        int n0 = lane >> 2;
        int k = (kg << 4) + ((lane & 3) << 1);
        int a = ngl;
        const float* b0 = A + (((size_t)a * NE + e) * K + k) * 16;
        __half h[8];
        h[0]=__float2half_rn(b0[n0]);            h[1]=__float2half_rn(b0[16 + n0]);
        h[2]=__float2half_rn(b0[8*16 + n0]);     h[3]=__float2half_rn(b0[9*16 + n0]);
        h[4]=__float2half_rn(b0[n0+8]);          h[5]=__float2half_rn(b0[16 + n0+8]);
        h[6]=__float2half_rn(b0[8*16 + n0+8]);   h[7]=__float2half_rn(b0[9*16 + n0+8]);
        __half* dst = (which == 2)
            ? g_Adt + ((((size_t)e*2 + ngl) * 64 + kg) * 32 + lane) * 8
            : g_Azt + ((((size_t)e*4 + (which << 1) + ngl) * 128 + kg) * 32 + lane) * 8;
        *(uint4*)dst = *(uint4*)h;
    }
}

// ---------------- unified fp16 grouped GEMM, 64-k double chunks ----------------
// EPI 0: half natural store (down)  1: fused gate|up -> h units in Gh
// EPI 2: masked Zgu -> Xg kgrps 128+  3: masked Zd -> Gh kgrps 64+
template<int N_, int EPI>
__global__ __launch_bounds__(256, 2)
void mm(const __half* __restrict__ X, int KGXp,
        const __half* __restrict__ Wt, int KGW, int NGT, int KT,
        void* __restrict__ OutV)
{
    if ((int)blockIdx.y >= g_nt) return;
    const int e   = g_te[blockIdx.y];
    const int m0  = g_tm[blockIdx.y] << 7;
    const int posbase = g_off[e] + m0;
    const int Pbase = posbase >> 4;
    const int n0  = blockIdx.x * N_;
    const int tid = threadIdx.x, lane = tid & 31, wid = tid >> 5;
    constexpr int MW = 256 / N_;
    constexpr int MF = 8 / MW;
    constexpr int XSB = 16384;                // X stage bytes (128 rows x 64 k)
    constexpr int WSB = N_ * 128;             // B stage bytes
    constexpr int STGB = XSB + WSB;
    const int rg0 = (wid % MW) * MF;          // row-group base (16-row units)
    const int cb4 = (wid / MW) * 2;           // ngroup base (2 ngroups per warp)

    extern __shared__ __half sm[];
    const uint32_t smb = smem_u32(sm);
    const size_t WB = (size_t)e * NGT + (n0 >> 4);

    auto issue = [&](int kc, int buf) {
        #pragma unroll
        for (int i = 0; i < 4; i++) {
            int u = tid + (i << 8);
            cpa16(smb + buf * STGB + u * 16,
                  X + (((size_t)(Pbase + (u >> 7)) * KGXp + (kc << 2) + ((u >> 5) & 3)) * 32 + (u & 31)) * 8);
        }
        #pragma unroll
        for (int i = 0; i < (N_ >> 5); i++) {
            int v = tid + (i << 8);
            cpa16(smb + buf * STGB + XSB + v * 16,
                  Wt + (((WB + (v >> 7)) * KGW + (kc << 2) + ((v >> 5) & 3)) * 32 + (v & 31)) * 8);
        }
    };

    float acc[MF][4][4];
    #pragma unroll
    for (int i = 0; i < MF; i++)
        #pragma unroll
        for (int j = 0; j < 4; j++) { acc[i][j][0]=0.f; acc[i][j][1]=0.f; acc[i][j][2]=0.f; acc[i][j][3]=0.f; }

    issue(0, 0); cpa_commit();
    issue(1, 1); cpa_commit();

    for (int kc = 0; kc < KT; kc++) {
        cpa_wait1();
        __syncthreads();
        if (kc + 2 < KT) issue(kc + 2, (kc + 2) % 3);
        cpa_commit();
        const __half* xs = sm + (kc % 3) * (STGB / 2);
        const __half* ws = xs + XSB / 2;
        #pragma unroll
        for (int ks = 0; ks < 4; ks++) {
            uint32_t A[MF][4];
            #pragma unroll
            for (int mf = 0; mf < MF; mf++) {
                uint4 q = *(const uint4*)(xs + ((((rg0 + mf) << 2) + ks) * 32 + lane) * 8);
                A[mf][0] = q.x; A[mf][1] = q.y; A[mf][2] = q.z; A[mf][3] = q.w;
            }
            uint32_t B[4][2];
            #pragma unroll
            for (int pi = 0; pi < 2; pi++) {
                uint4 q = *(const uint4*)(ws + ((((cb4 + pi) << 2) + ks) * 32 + lane) * 8);
                B[2*pi][0] = q.x; B[2*pi][1] = q.y;
                B[2*pi+1][0] = q.z; B[2*pi+1][1] = q.w;
            }
            #pragma unroll
            for (int mf = 0; mf < MF; mf++)
                #pragma unroll
                for (int nf = 0; nf < 4; nf++)
                    mma16(acc[mf][nf], A[mf], B[nf]);
        }
    }

    // ---------------- epilogue ----------------
    const int outlane = ((lane >> 2) << 2) + (lane & 3);
    #pragma unroll
    for (int mf = 0; mf < MF; mf++) {
        int rl0 = ((rg0 + mf) << 4) + (lane >> 2);
        int p0 = posbase + rl0;
        if (EPI == 0) {
            __half* Out = (__half*)OutV;
            #pragma unroll
            for (int nf = 0; nf < 4; nf++) {
                int cl = (cb4 << 4) + (nf << 3) + ((lane & 3) << 1);
                *(__half2*)(Out + (size_t)p0 * HD + n0 + cl) = h2f(acc[mf][nf][0], acc[mf][nf][1]);
                *(__half2*)(Out + (size_t)(p0 + 8) * HD + n0 + cl) = h2f(acc[mf][nf][2], acc[mf][nf][3]);
            }
        } else if (EPI == 1) {
            __half* Out = (__half*)OutV;
            int kq = ((n0 >> 1) + (cb4 << 3)) >> 4;
            float h[8];
            #pragma unroll
            for (int pi = 0; pi < 2; pi++) {
                #pragma unroll
                for (int q = 0; q < 4; q++) {
                    float g = acc[mf][2*pi][q], u = acc[mf][2*pi+1][q];
                    h[pi*4 + q] = u * g / (1.f + expf(-g));
                }
            }
            __half2 o[4] = { h2f(h[0],h[1]), h2f(h[2],h[3]), h2f(h[4],h[5]), h2f(h[6],h[7]) };
            size_t P = (size_t)(Pbase + rg0 + mf);
            *(uint4*)(Out + ((P * KGH + kq) * 32 + outlane) * 8) = *(uint4*)o;
        } else {
            __half* Out = (__half*)OutV;
            int a0 = g_adp[p0], a1 = g_adp[p0 + 8];
            size_t P = (size_t)(Pbase + rg0 + mf);
            #pragma unroll
            for (int P2 = 0; P2 < 2; P2++) {
                int slot = (cb4 + P2) & 1;
                int kq = (EPI == 2 ? 128 : 64) + cb4 + P2;
                float v0 = (slot == a0) ? 1.f : 0.f;
                float v1 = (slot == a1) ? 1.f : 0.f;
                __half2 o[4] = {
                    h2f(acc[mf][2*P2][0]*v0,   acc[mf][2*P2][1]*v0),
                    h2f(acc[mf][2*P2][2]*v1,   acc[mf][2*P2][3]*v1),
                    h2f(acc[mf][2*P2+1][0]*v0, acc[mf][2*P2+1][1]*v0),
                    h2f(acc[mf][2*P2+1][2]*v1, acc[mf][2*P2+1][3]*v1) };
                int KGO = (EPI == 2) ? KGX : KGH;
                *(uint4*)(Out + ((P * KGO + kq) * 32 + outlane) * 8) = *(uint4*)o;
            }
        }
    }
}

// ---------------- combine (half O) ----------------
__global__ void combine_kernel(const float* __restrict__ rw, float* __restrict__ out) {
    int t = blockIdx.x;
    __shared__ int s_pos[TOPK];
    __shared__ float s_w[TOPK];
    if (threadIdx.x < TOPK) {
        s_pos[threadIdx.x] = g_pos[t*TOPK + threadIdx.x];
        s_w[threadIdx.x]   = rw[t*TOPK + threadIdx.x];
    }
    __syncthreads();
    int h = threadIdx.x * 8;                  // 256 threads x 8 = 2048 = HD
    float acc[8] = {0.f,0.f,0.f,0.f,0.f,0.f,0.f,0.f};
    #pragma unroll
    for (int k = 0; k < TOPK; k++) {
        const __half2* v = (const __half2*)(g_O + (size_t)s_pos[k]*HD + h);
        float w = s_w[k];
        #pragma unroll
        for (int q = 0; q < 4; q++) {
            float2 f = __half22float2(v[q]);
            acc[2*q]   += w * f.x;
            acc[2*q+1] += w * f.y;
        }
    }
    float4* o = (float4*)(out + (size_t)t*HD + h);
    o[0] = make_float4(acc[0], acc[1], acc[2], acc[3]);
    o[1] = make_float4(acc[4], acc[5], acc[6], acc[7]);
}

#define SM128 (3*(16384 + 128*128))
#define SM64  (3*(16384 +  64*128))
#define SM32  (3*(16384 +  32*128))

extern "C" void kernel_launch(void* const* d_in, const int* in_sizes, int n_in,
                              void* d_out, int out_size) {
    const float* hidden = (const float*)d_in[0];
    const int*   sel    = (const int*)  d_in[1];
    const float* rw     = (const float*)d_in[2];
    const int*   adp    = (const int*)  d_in[3];
    const float* Wg     = (const float*)d_in[4];
    const float* Ag     = (const float*)d_in[5];
    const float* Bg     = (const float*)d_in[6];
    const float* Wu     = (const float*)d_in[7];
    const float* Au     = (const float*)d_in[8];
    const float* Bu     = (const float*)d_in[9];
    const float* Wd     = (const float*)d_in[10];
    const float* Ad     = (const float*)d_in[11];
    const float* Bd     = (const float*)d_in[12];
    float* out = (float*)d_out;

    static bool init = false;
    static cudaStream_t s1;
    static cudaEvent_t evRoot, evA, evGU, evD;
    if (!init) {
        cudaFuncSetAttribute(mm<128,0>, cudaFuncAttributeMaxDynamicSharedMemorySize, SM128);
        cudaFuncSetAttribute(mm<128,1>, cudaFuncAttributeMaxDynamicSharedMemorySize, SM128);
        cudaFuncSetAttribute(mm<64,2>,  cudaFuncAttributeMaxDynamicSharedMemorySize, SM64);
        cudaFuncSetAttribute(mm<32,3>,  cudaFuncAttributeMaxDynamicSharedMemorySize, SM32);
        cudaStreamCreateWithFlags(&s1, cudaStreamNonBlocking);
        cudaEventCreateWithFlags(&evRoot, cudaEventDisableTiming);
        cudaEventCreateWithFlags(&evA,    cudaEventDisableTiming);
        cudaEventCreateWithFlags(&evGU,   cudaEventDisableTiming);
        cudaEventCreateWithFlags(&evD,    cudaEventDisableTiming);
        init = true;
    }

    __half *Xg, *Gh, *O, *Wgu, *Wdp, *Azt, *Adt;
    cudaGetSymbolAddress((void**)&Xg,  g_Xg);
    cudaGetSymbolAddress((void**)&Gh,  g_Gh);
    cudaGetSymbolAddress((void**)&O,   g_O);
    cudaGetSymbolAddress((void**)&Wgu, g_Wgu);
    cudaGetSymbolAddress((void**)&Wdp, g_Wd);
    cudaGetSymbolAddress((void**)&Azt, g_Azt);
    cudaGetSymbolAddress((void**)&Adt, g_Adt);

    // ---- fork: weight/lora pre-passes on side stream ----
    cudaEventRecord(evRoot, 0);
    cudaStreamWaitEvent(s1, evRoot, 0);
    aconv<<<dim3(NE, 3), 256, 0, s1>>>(Ag, Au, Ad);
    cudaEventRecord(evA, s1);
    wconv_gu<<<dim3(16, 66, NE), 256, 0, s1>>>(Wg, Wu, Bg, Bu);
    cudaEventRecord(evGU, s1);
    wconv_d<<<dim3(16, 33, NE), 256, 0, s1>>>(Wd, Bd);
    cudaEventRecord(evD, s1);

    // ---- main stream: critical path ----
    routing_kernel<<<1, 1024>>>(sel, adp);
    xconv<<<MAXT*8, 256>>>(hidden);

    cudaStreamWaitEvent(0, evA, 0);    // need Azt/Adt
    // Z(gate|up) -> Xg kgrps 128..131 (adapter-masked); 32 double-chunks
    mm<64,2><<<dim3(1, MAXT), 256, SM64>>>(Xg, KGX, Azt, 128, 4, 32, Xg);

    cudaStreamWaitEvent(0, evGU, 0);   // need Wgu
    // fused gate+up -> Gh (h = silu(g)*u); 33 double-chunks
    mm<128,1><<<dim3(16, MAXT), 256, SM128>>>(Xg, KGX, Wgu, KGX, 128, 33, Gh);

    // Z(down) -> Gh kgrps 64..65; 16 double-chunks (Adt ready via evA)
    mm<32,3><<<dim3(1, MAXT), 256, SM32>>>(Gh, KGH, Adt, 64, 2, 16, Gh);

    cudaStreamWaitEvent(0, evD, 0);    // need Wd (joins side stream)
    // down -> O (half natural); 17 double-chunks (kg 66,67 zeros both sides)
    mm<128,0><<<dim3(16, MAXT), 256, SM128>>>(Gh, KGH, Wdp, KGH, 128, 17, O);

    combine_kernel<<<NT, 256>>>(rw, out);
}

// round 15
// speedup vs baseline: 3.0226x; 1.0149x over previous
#include <cuda_runtime.h>
#include <cuda_fp16.h>
#include <cstdint>
#include <math.h>

#define NE 32
#define TOPK 8
#define HD 2048
#define ID 1024
#define NT 4096
#define TE (NT*TOPK)
#define MAXT 288
#define PTE (MAXT*128)      // padded position space (128-aligned expert groups)

#define KGX 132             // Xg kgroups: 128 X | 2 Zg | 2 Zu   (16 k each)
#define KGH 68              // Gh kgroups: 64 h | 2 Zd | 2 zero-pad

__device__ int g_cnt[NE], g_off[NE], g_cur[NE];
__device__ int g_tok[PTE], g_adp[PTE], g_pos[TE];
__device__ int g_te[MAXT], g_tm[MAXT], g_nt;
__device__ __half g_Xg[(size_t)PTE*KGX*16];            // fragment units
__device__ __half g_Gh[(size_t)PTE*KGH*16];            // kg 66,67 stay zero (never written)
__device__ __half g_O [(size_t)PTE*HD];                // down output, fp16
__device__ __half g_Wgu[(size_t)NE*128*KGX*256];       // fused gate|up image
__device__ __half g_Wd [(size_t)NE*128*KGH*256];       // kg 66,67 stay zero
__device__ __half g_Azt[(size_t)NE*4*128*256];
__device__ __half g_Adt[(size_t)NE*2*64*256];

__device__ __forceinline__ uint32_t smem_u32(const void* p) {
    uint32_t a;
    asm("{ .reg .u64 t; cvta.to.shared.u64 t, %1; cvt.u32.u64 %0, t; }" : "=r"(a) : "l"(p));
    return a;
}
__device__ __forceinline__ void cpa16(uint32_t dst, const void* src) {
    asm volatile("cp.async.cg.shared.global [%0], [%1], 16;" :: "r"(dst), "l"(src) : "memory");
}
__device__ __forceinline__ void cpa_commit() { asm volatile("cp.async.commit_group;" ::: "memory"); }
__device__ __forceinline__ void cpa_wait1()  { asm volatile("cp.async.wait_group 1;" ::: "memory"); }
__device__ __forceinline__ void mma16(float* c, const uint32_t* a, const uint32_t* b) {
    asm volatile(
        "mma.sync.aligned.m16n8k16.row.col.f32.f16.f16.f32 "
        "{%0,%1,%2,%3}, {%4,%5,%6,%7}, {%8,%9}, {%0,%1,%2,%3};\n"
        : "+f"(c[0]), "+f"(c[1]), "+f"(c[2]), "+f"(c[3])
        : "r"(a[0]), "r"(a[1]), "r"(a[2]), "r"(a[3]), "r"(b[0]), "r"(b[1]));
}
__device__ __forceinline__ __half2 h2f(float x, float y) {
    return __halves2half2(__float2half_rn(x), __float2half_rn(y));
}

// ---------------- routing (parallel): zcnt -> count -> scan -> scatter ----------------
__global__ void zcnt_kernel() {
    if (threadIdx.x < NE) g_cnt[threadIdx.x] = 0;
}

__global__ void count_kernel(const int* __restrict__ sel) {
    __shared__ int c[NE];
    int tid = threadIdx.x;
    if (tid < NE) c[tid] = 0;
    __syncthreads();
    int stride = gridDim.x * blockDim.x;
    for (int i = blockIdx.x * blockDim.x + tid; i < TE; i += stride)
        atomicAdd(&c[sel[i]], 1);
    // zero padded-position arrays in parallel (no conflict with counting)
    for (int p = blockIdx.x * blockDim.x + tid; p < PTE; p += stride) {
        g_tok[p] = 0; g_adp[p] = 0;
    }
    __syncthreads();
    if (tid < NE && c[tid]) atomicAdd(&g_cnt[tid], c[tid]);
}

__global__ void scan_kernel() {
    if (threadIdx.x == 0) {
        int acc = 0, idx = 0;
        for (int e = 0; e < NE; e++) {
            int c = g_cnt[e];
            g_off[e] = acc; g_cur[e] = acc;
            int tl = (c + 127) >> 7;
            for (int i = 0; i < tl; i++) { g_te[idx] = e; g_tm[idx] = i; idx++; }
            acc += tl << 7;             // 128-aligned
        }
        g_nt = idx;
    }
}

__global__ void scatter_kernel(const int* __restrict__ sel, const int* __restrict__ adp) {
    int i = blockIdx.x * blockDim.x + threadIdx.x;
    if (i >= TE) return;
    int e = sel[i];
    int pos = atomicAdd(&g_cur[e], 1);
    int t = i >> 3;
    g_tok[pos] = t; g_adp[pos] = adp[t]; g_pos[i] = pos;
}

// ---------------- X pre-pass: gather + half + fragment units ----------------
__global__ void xconv(const float* __restrict__ hidden) {
    int P = blockIdx.x;
    if (P >= g_nt * 8) return;
    __shared__ int tk[16];
    int tid = threadIdx.x;
    if (tid < 16) tk[tid] = g_tok[P * 16 + tid];
    __syncthreads();
    #pragma unroll
    for (int i = 0; i < 16; i++) {
        int id = tid + (i << 8);               // 4096 units: kg 0..127, lane 0..31
        int kg = id >> 5, lane = id & 31;
        int r0 = lane >> 2;
        int kl = (kg << 4) + ((lane & 3) << 1);
        const float* s0 = hidden + (size_t)tk[r0] * HD;
        const float* s1 = hidden + (size_t)tk[r0 + 8] * HD;
        float2 a0 = *(const float2*)(s0 + kl);
        float2 a1 = *(const float2*)(s1 + kl);
        float2 b0 = *(const float2*)(s0 + kl + 8);
        float2 b1 = *(const float2*)(s1 + kl + 8);
        __half2 o[4] = { h2f(a0.x, a0.y), h2f(a1.x, a1.y), h2f(b0.x, b0.y), h2f(b1.x, b1.y) };
        *(uint4*)(g_Xg + (((size_t)P * KGX + kg) * 32 + lane) * 8) = *(uint4*)o;
    }
}

// ---------------- fused gate|up weight pre-pass ----------------
__global__ void wconv_gu(const float* __restrict__ Wg, const float* __restrict__ Wu,
                         const float* __restrict__ Bg, const float* __restrict__ Bu)
{
    __shared__ float sg[32][68], su[32][68];
    int e = blockIdx.z, ky = blockIdx.y, x = blockIdx.x;   // x: 64 real cols
    int tid = threadIdx.x;
    int rc0 = x << 6;
    #pragma unroll
    for (int i = 0; i < 2; i++) {
        int u = tid + (i << 8);
        int kk = u >> 4, c4 = (u & 15) << 2;
        float4 vg = make_float4(0,0,0,0), vu = vg;
        if (ky < 64) {
            vg = *(const float4*)(Wg + ((size_t)e * HD + (ky << 5) + kk) * ID + rc0 + c4);
            vu = *(const float4*)(Wu + ((size_t)e * HD + (ky << 5) + kk) * ID + rc0 + c4);
        } else if (ky == 64) {
            vg = *(const float4*)(Bg + (((size_t)(kk >> 4) * NE + e) * 16 + (kk & 15)) * ID + rc0 + c4);
        } else {
            vu = *(const float4*)(Bu + (((size_t)(kk >> 4) * NE + e) * 16 + (kk & 15)) * ID + rc0 + c4);
        }
        sg[kk][c4]=vg.x; sg[kk][c4+1]=vg.y; sg[kk][c4+2]=vg.z; sg[kk][c4+3]=vg.w;
        su[kk][c4]=vu.x; su[kk][c4+1]=vu.y; su[kk][c4+2]=vu.z; su[kk][c4+3]=vu.w;
    }
    __syncthreads();
    #pragma unroll
    for (int i = 0; i < 2; i++) {
        int u = tid + (i << 8);
        int ngl = u >> 6, kg = (u >> 5) & 1, lane = u & 31;
        int gc = (ngl << 3) + (lane >> 2);
        int kl = (kg << 4) + ((lane & 3) << 1);
        __half h[8];
        h[0]=__float2half_rn(sg[kl][gc]);   h[1]=__float2half_rn(sg[kl+1][gc]);
        h[2]=__float2half_rn(sg[kl+8][gc]); h[3]=__float2half_rn(sg[kl+9][gc]);
        h[4]=__float2half_rn(su[kl][gc]);   h[5]=__float2half_rn(su[kl+1][gc]);
        h[6]=__float2half_rn(su[kl+8][gc]); h[7]=__float2half_rn(su[kl+9][gc]);
        *(uint4*)(g_Wgu + ((((size_t)e*128 + (x<<3) + ngl) * KGX + (ky<<1) + kg) * 32 + lane) * 8) = *(uint4*)h;
    }
}

// ---------------- down weight pre-pass ----------------
__global__ void wconv_d(const float* __restrict__ Wd, const float* __restrict__ Bd) {
    __shared__ float s[32][132];
    int e = blockIdx.z, ky = blockIdx.y, x = blockIdx.x;
    int tid = threadIdx.x;
    int n0 = x << 7;
    #pragma unroll
    for (int i = 0; i < 4; i++) {
        int u = tid + (i << 8);
        int kk = u >> 5, c4 = (u & 31) << 2;
        float4 v;
        if (ky < 32) v = *(const float4*)(Wd + ((size_t)e * ID + (ky << 5) + kk) * HD + n0 + c4);
        else         v = *(const float4*)(Bd + (((size_t)(kk >> 4) * NE + e) * 16 + (kk & 15)) * HD + n0 + c4);
        s[kk][c4]=v.x; s[kk][c4+1]=v.y; s[kk][c4+2]=v.z; s[kk][c4+3]=v.w;
    }
    __syncthreads();
    #pragma unroll
    for (int i = 0; i < 2; i++) {
        int u = tid + (i << 8);
        int ngl = u >> 6, kg = (u >> 5) & 1, lane = u & 31;
        int c = (ngl << 4) + (lane >> 2);
        int kl = (kg << 4) + ((lane & 3) << 1);
        __half h[8];
        h[0]=__float2half_rn(s[kl][c]);     h[1]=__float2half_rn(s[kl+1][c]);
        h[2]=__float2half_rn(s[kl+8][c]);   h[3]=__float2half_rn(s[kl+9][c]);
        h[4]=__float2half_rn(s[kl][c+8]);   h[5]=__float2half_rn(s[kl+1][c+8]);
        h[6]=__float2half_rn(s[kl+8][c+8]); h[7]=__float2half_rn(s[kl+9][c+8]);
        *(uint4*)(g_Wd + ((((size_t)e*128 + (x<<3) + ngl) * KGH + (ky<<1) + kg) * 32 + lane) * 8) = *(uint4*)h;
    }
}

// ---------------- loraA pre-pass (fragment units) ----------------
__global__ void aconv(const float* __restrict__ Ag, const float* __restrict__ Au,
                      const float* __restrict__ Ad)
{
    int e = blockIdx.x, which = blockIdx.y, tid = threadIdx.x;
    int K = (which == 2) ? ID : HD;
    int KG = K >> 4;
    const float* A = (which == 0) ? Ag : (which == 1) ? Au : Ad;
    int units = 2 * KG * 32;
    for (int u = tid; u < units; u += 256) {
        int ngl = u / (KG * 32);
        int rem = u - ngl * KG * 32;
        int kg = rem >> 5, lane = rem & 31;
        int n0 = lane >> 2;
        int k = (kg << 4) + ((lane & 3) << 1);
        int a = ngl;
        const float* b0 = A + (((size_t)a * NE + e) * K + k) * 16;
        __half h[8];
        h[0]=__float2half_rn(b0[n0]);            h[1]=__float2half_rn(b0[16 + n0]);
        h[2]=__float2half_rn(b0[8*16 + n0]);     h[3]=__float2half_rn(b0[9*16 + n0]);
        h[4]=__float2half_rn(b0[n0+8]);          h[5]=__float2half_rn(b0[16 + n0+8]);
        h[6]=__float2half_rn(b0[8*16 + n0+8]);   h[7]=__float2half_rn(b0[9*16 + n0+8]);
        __half* dst = (which == 2)
            ? g_Adt + ((((size_t)e*2 + ngl) * 64 + kg) * 32 + lane) * 8
            : g_Azt + ((((size_t)e*4 + (which << 1) + ngl) * 128 + kg) * 32 + lane) * 8;
        *(uint4*)dst = *(uint4*)h;
    }
}

// ---------------- unified fp16 grouped GEMM, 64-k double chunks ----------------
// EPI 0: half natural store (down)  1: fused gate|up -> h units in Gh
// EPI 2: masked Zgu -> Xg kgrps 128+  3: masked Zd -> Gh kgrps 64+
template<int N_, int EPI>
__global__ __launch_bounds__(256, 2)
void mm(const __half* __restrict__ X, int KGXp,
        const __half* __restrict__ Wt, int KGW, int NGT, int KT,
        void* __restrict__ OutV)
{
    if ((int)blockIdx.y >= g_nt) return;
    const int e   = g_te[blockIdx.y];
    const int m0  = g_tm[blockIdx.y] << 7;
    const int posbase = g_off[e] + m0;
    const int Pbase = posbase >> 4;
    const int n0  = blockIdx.x * N_;
    const int tid = threadIdx.x, lane = tid & 31, wid = tid >> 5;
    constexpr int MW = 256 / N_;
    constexpr int MF = 8 / MW;
    constexpr int XSB = 16384;                // X stage bytes (128 rows x 64 k)
    constexpr int WSB = N_ * 128;             // B stage bytes
    constexpr int STGB = XSB + WSB;
    const int rg0 = (wid % MW) * MF;          // row-group base (16-row units)
    const int cb4 = (wid / MW) * 2;           // ngroup base (2 ngroups per warp)

    extern __shared__ __half sm[];
    const uint32_t smb = smem_u32(sm);
    const size_t WB = (size_t)e * NGT + (n0 >> 4);

    auto issue = [&](int kc, int buf) {
        #pragma unroll
        for (int i = 0; i < 4; i++) {
            int u = tid + (i << 8);
            cpa16(smb + buf * STGB + u * 16,
                  X + (((size_t)(Pbase + (u >> 7)) * KGXp + (kc << 2) + ((u >> 5) & 3)) * 32 + (u & 31)) * 8);
        }
        #pragma unroll
        for (int i = 0; i < (N_ >> 5); i++) {
            int v = tid + (i << 8);
            cpa16(smb + buf * STGB + XSB + v * 16,
                  Wt + (((WB + (v >> 7)) * KGW + (kc << 2) + ((v >> 5) & 3)) * 32 + (v & 31)) * 8);
        }
    };

    float acc[MF][4][4];
    #pragma unroll
    for (int i = 0; i < MF; i++)
        #pragma unroll
        for (int j = 0; j < 4; j++) { acc[i][j][0]=0.f; acc[i][j][1]=0.f; acc[i][j][2]=0.f; acc[i][j][3]=0.f; }

    issue(0, 0); cpa_commit();
    issue(1, 1); cpa_commit();

    for (int kc = 0; kc < KT; kc++) {
        cpa_wait1();
        __syncthreads();
        if (kc + 2 < KT) issue(kc + 2, (kc + 2) % 3);
        cpa_commit();
        const __half* xs = sm + (kc % 3) * (STGB / 2);
        const __half* ws = xs + XSB / 2;
        #pragma unroll
        for (int ks = 0; ks < 4; ks++) {
            uint32_t A[MF][4];
            #pragma unroll
            for (int mf = 0; mf < MF; mf++) {
                uint4 q = *(const uint4*)(xs + ((((rg0 + mf) << 2) + ks) * 32 + lane) * 8);
                A[mf][0] = q.x; A[mf][1] = q.y; A[mf][2] = q.z; A[mf][3] = q.w;
            }
            uint32_t B[4][2];
            #pragma unroll
            for (int pi = 0; pi < 2; pi++) {
                uint4 q = *(const uint4*)(ws + ((((cb4 + pi) << 2) + ks) * 32 + lane) * 8);
                B[2*pi][0] = q.x; B[2*pi][1] = q.y;
                B[2*pi+1][0] = q.z; B[2*pi+1][1] = q.w;
            }
            #pragma unroll
            for (int mf = 0; mf < MF; mf++)
                #pragma unroll
                for (int nf = 0; nf < 4; nf++)
                    mma16(acc[mf][nf], A[mf], B[nf]);
        }
    }

    // ---------------- epilogue ----------------
    const int outlane = ((lane >> 2) << 2) + (lane & 3);
    #pragma unroll
    for (int mf = 0; mf < MF; mf++) {
        int rl0 = ((rg0 + mf) << 4) + (lane >> 2);
        int p0 = posbase + rl0;
        if (EPI == 0) {
            __half* Out = (__half*)OutV;
            #pragma unroll
            for (int nf = 0; nf < 4; nf++) {
                int cl = (cb4 << 4) + (nf << 3) + ((lane & 3) << 1);
                *(__half2*)(Out + (size_t)p0 * HD + n0 + cl) = h2f(acc[mf][nf][0], acc[mf][nf][1]);
                *(__half2*)(Out + (size_t)(p0 + 8) * HD + n0 + cl) = h2f(acc[mf][nf][2], acc[mf][nf][3]);
            }
        } else if (EPI == 1) {
            __half* Out = (__half*)OutV;
            int kq = ((n0 >> 1) + (cb4 << 3)) >> 4;
            float h[8];
            #pragma unroll
            for (int pi = 0; pi < 2; pi++) {
                #pragma unroll
                for (int q = 0; q < 4; q++) {
                    float g = acc[mf][2*pi][q], u = acc[mf][2*pi+1][q];
                    h[pi*4 + q] = u * g / (1.f + __expf(-g));
                }
            }
            __half2 o[4] = { h2f(h[0],h[1]), h2f(h[2],h[3]), h2f(h[4],h[5]), h2f(h[6],h[7]) };
            size_t P = (size_t)(Pbase + rg0 + mf);
            *(uint4*)(Out + ((P * KGH + kq) * 32 + outlane) * 8) = *(uint4*)o;
        } else {
            __half* Out = (__half*)OutV;
            int a0 = g_adp[p0], a1 = g_adp[p0 + 8];
            size_t P = (size_t)(Pbase + rg0 + mf);
            #pragma unroll
            for (int P2 = 0; P2 < 2; P2++) {
                int slot = (cb4 + P2) & 1;
                int kq = (EPI == 2 ? 128 : 64) + cb4 + P2;
                float v0 = (slot == a0) ? 1.f : 0.f;
                float v1 = (slot == a1) ? 1.f : 0.f;
                __half2 o[4] = {
                    h2f(acc[mf][2*P2][0]*v0,   acc[mf][2*P2][1]*v0),
                    h2f(acc[mf][2*P2][2]*v1,   acc[mf][2*P2][3]*v1),
                    h2f(acc[mf][2*P2+1][0]*v0, acc[mf][2*P2+1][1]*v0),
                    h2f(acc[mf][2*P2+1][2]*v1, acc[mf][2*P2+1][3]*v1) };
                int KGO = (EPI == 2) ? KGX : KGH;
                *(uint4*)(Out + ((P * KGO + kq) * 32 + outlane) * 8) = *(uint4*)o;
            }
        }
    }
}

// ---------------- combine (half O) ----------------
__global__ void combine_kernel(const float* __restrict__ rw, float* __restrict__ out) {
    int t = blockIdx.x;
    __shared__ int s_pos[TOPK];
    __shared__ float s_w[TOPK];
    if (threadIdx.x < TOPK) {
        s_pos[threadIdx.x] = g_pos[t*TOPK + threadIdx.x];
        s_w[threadIdx.x]   = rw[t*TOPK + threadIdx.x];
    }
    __syncthreads();
    int h = threadIdx.x * 8;                  // 256 threads x 8 = 2048 = HD
    float acc[8] = {0.f,0.f,0.f,0.f,0.f,0.f,0.f,0.f};
    #pragma unroll
    for (int k = 0; k < TOPK; k++) {
        const __half2* v = (const __half2*)(g_O + (size_t)s_pos[k]*HD + h);
        float w = s_w[k];
        #pragma unroll
        for (int q = 0; q < 4; q++) {
            float2 f = __half22float2(v[q]);
            acc[2*q]   += w * f.x;
            acc[2*q+1] += w * f.y;
        }
    }
    float4* o = (float4*)(out + (size_t)t*HD + h);
    o[0] = make_float4(acc[0], acc[1], acc[2], acc[3]);
    o[1] = make_float4(acc[4], acc[5], acc[6], acc[7]);
}

#define SM128 (3*(16384 + 128*128))
#define SM64  (3*(16384 +  64*128))
#define SM32  (3*(16384 +  32*128))

extern "C" void kernel_launch(void* const* d_in, const int* in_sizes, int n_in,
                              void* d_out, int out_size) {
    const float* hidden = (const float*)d_in[0];
    const int*   sel    = (const int*)  d_in[1];
    const float* rw     = (const float*)d_in[2];
    const int*   adp    = (const int*)  d_in[3];
    const float* Wg     = (const float*)d_in[4];
    const float* Ag     = (const float*)d_in[5];
    const float* Bg     = (const float*)d_in[6];
    const float* Wu     = (const float*)d_in[7];
    const float* Au     = (const float*)d_in[8];
    const float* Bu     = (const float*)d_in[9];
    const float* Wd     = (const float*)d_in[10];
    const float* Ad     = (const float*)d_in[11];
    const float* Bd     = (const float*)d_in[12];
    float* out = (float*)d_out;

    static bool init = false;
    static cudaStream_t s1;
    static cudaEvent_t evRoot, evA, evGU, evD;
    if (!init) {
        cudaFuncSetAttribute(mm<128,0>, cudaFuncAttributeMaxDynamicSharedMemorySize, SM128);
        cudaFuncSetAttribute(mm<128,1>, cudaFuncAttributeMaxDynamicSharedMemorySize, SM128);
        cudaFuncSetAttribute(mm<64,2>,  cudaFuncAttributeMaxDynamicSharedMemorySize, SM64);
        cudaFuncSetAttribute(mm<32,3>,  cudaFuncAttributeMaxDynamicSharedMemorySize, SM32);
        cudaStreamCreateWithFlags(&s1, cudaStreamNonBlocking);
        cudaEventCreateWithFlags(&evRoot, cudaEventDisableTiming);
        cudaEventCreateWithFlags(&evA,    cudaEventDisableTiming);
        cudaEventCreateWithFlags(&evGU,   cudaEventDisableTiming);
        cudaEventCreateWithFlags(&evD,    cudaEventDisableTiming);
        init = true;
    }

    __half *Xg, *Gh, *O, *Wgu, *Wdp, *Azt, *Adt;
    cudaGetSymbolAddress((void**)&Xg,  g_Xg);
    cudaGetSymbolAddress((void**)&Gh,  g_Gh);
    cudaGetSymbolAddress((void**)&O,   g_O);
    cudaGetSymbolAddress((void**)&Wgu, g_Wgu);
    cudaGetSymbolAddress((void**)&Wdp, g_Wd);
    cudaGetSymbolAddress((void**)&Azt, g_Azt);
    cudaGetSymbolAddress((void**)&Adt, g_Adt);

    // ---- fork: weight/lora pre-passes on side stream ----
    cudaEventRecord(evRoot, 0);
    cudaStreamWaitEvent(s1, evRoot, 0);
    aconv<<<dim3(NE, 3), 256, 0, s1>>>(Ag, Au, Ad);
    cudaEventRecord(evA, s1);
    wconv_gu<<<dim3(16, 66, NE), 256, 0, s1>>>(Wg, Wu, Bg, Bu);
    cudaEventRecord(evGU, s1);
    wconv_d<<<dim3(16, 33, NE), 256, 0, s1>>>(Wd, Bd);
    cudaEventRecord(evD, s1);

    // ---- main stream: critical path ----
    zcnt_kernel<<<1, 32>>>();
    count_kernel<<<128, 256>>>(sel);
    scan_kernel<<<1, 32>>>();
    scatter_kernel<<<128, 256>>>(sel, adp);
    xconv<<<MAXT*8, 256>>>(hidden);

    cudaStreamWaitEvent(0, evA, 0);    // need Azt/Adt
    // Z(gate|up) -> Xg kgrps 128..131 (adapter-masked); 32 double-chunks
    mm<64,2><<<dim3(1, MAXT), 256, SM64>>>(Xg, KGX, Azt, 128, 4, 32, Xg);

    cudaStreamWaitEvent(0, evGU, 0);   // need Wgu
    // fused gate+up -> Gh (h = silu(g)*u); 33 double-chunks
    mm<128,1><<<dim3(16, MAXT), 256, SM128>>>(Xg, KGX, Wgu, KGX, 128, 33, Gh);

    // Z(down) -> Gh kgrps 64..65; 16 double-chunks (Adt ready via evA)
    mm<32,3><<<dim3(1, MAXT), 256, SM32>>>(Gh, KGH, Adt, 64, 2, 16, Gh);

    cudaStreamWaitEvent(0, evD, 0);    // need Wd (joins side stream)
    // down -> O (half natural); 17 double-chunks (kg 66,67 zeros both sides)
    mm<128,0><<<dim3(16, MAXT), 256, SM128>>>(Gh, KGH, Wdp, KGH, 128, 17, O);

    combine_kernel<<<NT, 256>>>(rw, out);
}